// round 6
// baseline (speedup 1.0000x reference)
#include <cuda_runtime.h>
#include <cuda_bf16.h>
#include <cstdint>
#include <math.h>

#define BATCH 8
#define LSEQ  1024
#define DIM   512
#define DI    1024
#define DS    16
#define HID   1024
#define ROWS  (BATCH*LSEQ)    // 8192

typedef __nv_bfloat16 bf16;

// ---------------- fp32 scratch ----------------
__device__ float g_pos    [LSEQ*DIM];
__device__ float g_pos_mix[LSEQ*DIM];
__device__ float g_xz     [ROWS*4096];
__device__ float g_xc     [2*ROWS*DI];
__device__ float g_proj   [2*ROWS*64];
__device__ float g_dsp    [2*ROWS*DI];
__device__ float g_dmix   [ROWS*DIM];
__device__ float g_dln    [ROWS*DIM];

// ---------------- bf16 hi/lo scratch ----------------
__device__ __align__(16) bf16 hl_scan_in[2*ROWS*DIM];
__device__ __align__(16) bf16 hl_pos_h  [2*LSEQ*DIM];
__device__ __align__(16) bf16 hl_pos    [2*LSEQ*DIM];
__device__ __align__(16) bf16 hl_w_pos2 [2*DIM*DIM];
__device__ __align__(16) bf16 hl_w_pmix [2*DIM*DIM];
__device__ __align__(16) bf16 hl_w_mixA [2*2*DIM*DIM];
__device__ __align__(16) bf16 hl_wT_out [2*2*DI*DIM];
__device__ __align__(16) bf16 hl_w_in   [2*4096*DIM];
__device__ __align__(16) bf16 hl_w_xp   [2*2*64*DI];
__device__ __align__(16) bf16 hl_w_dt   [2*2*DI*32];
__device__ __align__(16) bf16 hl_w_f1   [2*HID*DIM];
__device__ __align__(16) bf16 hl_w_f2   [2*DIM*HID];
__device__ __align__(16) bf16 hl_xc     [2*2*ROWS*DI];
__device__ __align__(16) bf16 hl_proj   [2*2*ROWS*64];
__device__ __align__(16) bf16 hl_ycat   [2*ROWS*2048];
__device__ __align__(16) bf16 hl_wc     [2*DIM*2048];
__device__ __align__(16) bf16 hl_lnf    [2*ROWS*DIM];
__device__ __align__(16) bf16 hl_h1     [2*ROWS*HID];

// ---------------- math helpers ----------------
__device__ __forceinline__ float geluf(float x) {
    return 0.5f * x * (1.0f + erff(x * 0.70710678118654752440f));
}
__device__ __forceinline__ float siluf(float x) { return x / (1.0f + __expf(-x)); }
__device__ __forceinline__ float softplusf(float x) { return (x > 20.0f) ? x : log1pf(__expf(x)); }
__device__ __forceinline__ void splitf(float v, bf16& h, bf16& l) {
    h = __float2bfloat16(v);
    l = __float2bfloat16(v - __bfloat162float(h));
}

// ---------------- PTX helpers ----------------
__device__ __forceinline__ void mma16816(float* d, const uint32_t* a, uint32_t b0, uint32_t b1) {
    asm volatile(
        "mma.sync.aligned.m16n8k16.row.col.f32.bf16.bf16.f32 "
        "{%0,%1,%2,%3},{%4,%5,%6,%7},{%8,%9},{%0,%1,%2,%3};\n"
        : "+f"(d[0]), "+f"(d[1]), "+f"(d[2]), "+f"(d[3])
        : "r"(a[0]), "r"(a[1]), "r"(a[2]), "r"(a[3]), "r"(b0), "r"(b1));
}
__device__ __forceinline__ void ldsm4(uint32_t* r, uint32_t addr) {
    asm volatile("ldmatrix.sync.aligned.m8n8.x4.shared.b16 {%0,%1,%2,%3}, [%4];\n"
                 : "=r"(r[0]), "=r"(r[1]), "=r"(r[2]), "=r"(r[3]) : "r"(addr));
}
__device__ __forceinline__ void cp16(uint32_t dst, const void* src, bool pred) {
    int sz = pred ? 16 : 0;
    asm volatile("cp.async.cg.shared.global [%0], [%1], 16, %2;\n"
                 :: "r"(dst), "l"(src), "r"(sz) : "memory");
}
__device__ __forceinline__ void cp_commit() { asm volatile("cp.async.commit_group;\n" ::: "memory"); }
__device__ __forceinline__ void cp_wait1()  { asm volatile("cp.async.wait_group 1;\n" ::: "memory"); }

// ================= 128x256 tensor GEMM (big shapes; N%256==0, M%128==0, K%32==0) ===========
// C[m,n] = sum_k A[m,k]*B[n,k], hi/lo 3-term.
// EPI: 0 none, 1 gelu, 4 +aux[(m%auxMod)*ldc+n], 5 +aux[m*ldc+n]
// OUT: 0 fp32 only, 2 hi/lo only
#define BG2_STAGE 49152
#define BG2_SMEM  (3*BG2_STAGE)

template<int EPI, int OUT>
__global__ void __launch_bounds__(256)
bgemm2(const bf16* __restrict__ Ah, const bf16* __restrict__ Al, int lda,
       const bf16* __restrict__ Bh, const bf16* __restrict__ Bl, int ldb,
       float* __restrict__ C, int ldc,
       bf16* __restrict__ Ch, long long planeC, int ldch,
       const float* __restrict__ bias,
       const float* __restrict__ aux, int auxMod,
       int K)
{
    extern __shared__ char smd[];
    const int bm = blockIdx.y * 128;
    const int bn = blockIdx.x * 256;
    const int tid = threadIdx.x, lane = tid & 31, warp = tid >> 5;
    const int wm = warp & 1, wn = warp >> 1;   // 2 x 4 warps, warp tile 64x64

    const uint32_t smem_base = (uint32_t)__cvta_generic_to_shared(smd);

    auto load_stage = [&](int s, int kt) {
        const int k0 = kt * 32;
        const uint32_t As = smem_base + s * BG2_STAGE;
        const uint32_t Bs = As + 16384;
#pragma unroll
        for (int i = 0; i < 4; i++) {           // A: 1024 granules
            int lin = i * 256 + tid;
            int row = lin >> 3, ch = lin & 7;
            const bf16* srcA = ((ch & 4) ? Al : Ah) + (size_t)(bm + row) * lda + k0 + (ch & 3) * 8;
            cp16(As + row * 128 + ((ch ^ (row & 7)) * 16), srcA, true);
        }
#pragma unroll
        for (int i = 0; i < 8; i++) {           // B: 2048 granules
            int lin = i * 256 + tid;
            int row = lin >> 3, ch = lin & 7;
            const bf16* srcB = ((ch & 4) ? Bl : Bh) + (size_t)(bn + row) * ldb + k0 + (ch & 3) * 8;
            cp16(Bs + row * 128 + ((ch ^ (row & 7)) * 16), srcB, true);
        }
    };

    float acc[4][8][4];
#pragma unroll
    for (int i = 0; i < 4; i++)
#pragma unroll
        for (int j = 0; j < 8; j++)
#pragma unroll
            for (int q = 0; q < 4; q++) acc[i][j][q] = 0.0f;

    const int nk = K / 32;
    load_stage(0, 0);
    cp_commit();
    if (nk > 1) load_stage(1, 1);
    cp_commit();

    const int g  = lane >> 3;
    const int lr = lane & 7;
    const int aRow0 = wm * 64 + (g & 1) * 8 + lr;
    const int bRow0 = wn * 64 + (g & 1) * 8 + lr;
    const int chHi  = (g >> 1);

    for (int kt = 0; kt < nk; kt++) {
        cp_wait1();
        __syncthreads();
        const uint32_t As = smem_base + (kt % 3) * BG2_STAGE;
        const uint32_t Bs = As + 16384;

#pragma unroll
        for (int step = 0; step < 2; step++) {
            const int cH = ((step * 2 + chHi) ^ lr) * 16;
            const int cL = ((4 + step * 2 + chHi) ^ lr) * 16;
            uint32_t ah[4][4], al[4][4];
#pragma unroll
            for (int mt = 0; mt < 4; mt++) {
                uint32_t rb = As + (uint32_t)(aRow0 + mt * 16) * 128;
                ldsm4(ah[mt], rb + cH);
                ldsm4(al[mt], rb + cL);
            }
#pragma unroll
            for (int ph = 0; ph < 2; ph++) {    // B column pairs {0,1},{2,3}
                uint32_t bh[2][4], bl[2][4];
#pragma unroll
                for (int pp = 0; pp < 2; pp++) {
                    uint32_t rb = Bs + (uint32_t)(bRow0 + (ph * 2 + pp) * 16) * 128;
                    ldsm4(bh[pp], rb + cH);
                    ldsm4(bl[pp], rb + cL);
                }
#pragma unroll
                for (int ntl = 0; ntl < 4; ntl++) {
                    const int nt = ph * 4 + ntl;
                    const int pp = ntl >> 1, o = ntl & 1;
                    const uint32_t b0h = bh[pp][o], b1h = bh[pp][o + 2];
                    const uint32_t b0l = bl[pp][o], b1l = bl[pp][o + 2];
#pragma unroll
                    for (int mt = 0; mt < 4; mt++) {
                        mma16816(acc[mt][nt], ah[mt], b0h, b1h);
                        mma16816(acc[mt][nt], ah[mt], b0l, b1l);
                        mma16816(acc[mt][nt], al[mt], b0h, b1h);
                    }
                }
            }
        }
        __syncthreads();
        if (kt + 2 < nk) load_stage((kt + 2) % 3, kt + 2);
        cp_commit();
    }

    const int r_ep = lane >> 2, c_ep = lane & 3;
#pragma unroll
    for (int mt = 0; mt < 4; mt++) {
        const int m0 = bm + wm * 64 + mt * 16 + r_ep;
#pragma unroll
        for (int nt = 0; nt < 8; nt++) {
            const int n0 = bn + wn * 64 + nt * 8 + 2 * c_ep;
#pragma unroll
            for (int half = 0; half < 2; half++) {
                const int m = m0 + half * 8;
#pragma unroll
                for (int q = 0; q < 2; q++) {
                    const int n = n0 + q;
                    float v = acc[mt][nt][half * 2 + q];
                    if (bias) v += bias[n];
                    if (EPI == 1)      v = geluf(v);
                    else if (EPI == 4) v += aux[(size_t)(m % auxMod) * ldc + n];
                    else if (EPI == 5) v += aux[(size_t)m * ldc + n];
                    if (OUT != 2) C[(size_t)m * ldc + n] = v;
                    if (OUT == 2) {
                        bf16 h, l; splitf(v, h, l);
                        size_t o = (size_t)m * ldch + n;
                        Ch[o] = h; Ch[planeC + o] = l;
                    }
                }
            }
        }
    }
}

// ---------------- 128x128 mma.sync GEMM (small/odd shapes; proven R3 config) ----------------
#define BK_STAGES 3
#define SMEM_BYTES (BK_STAGES*32768)

template<int EPI, int OUT>
__global__ void __launch_bounds__(256)
bgemm(const bf16* __restrict__ Ah, const bf16* __restrict__ Al, int lda, long long sA,
      const bf16* __restrict__ Bh, const bf16* __restrict__ Bl, int ldb, long long sB,
      float* __restrict__ C, int ldc, long long sC,
      bf16* __restrict__ Ch, long long planeC, int ldch, long long sCh,
      const float* __restrict__ bias, long long sBias,
      const float* __restrict__ aux, int auxMod,
      int M, int N, int K)
{
    extern __shared__ char smd[];
    const int zi = blockIdx.z;
    Ah += (size_t)zi * sA; Al += (size_t)zi * sA;
    Bh += (size_t)zi * sB; Bl += (size_t)zi * sB;
    if (OUT != 2) C += (size_t)zi * sC;
    if (OUT != 0) Ch += (size_t)zi * sCh;
    const float* bp = bias ? (bias + (size_t)zi * sBias) : nullptr;

    const int bm = blockIdx.y * 128;
    const int bn = blockIdx.x * 128;
    const int tid = threadIdx.x, lane = tid & 31, warp = tid >> 5;
    const int wm = warp & 1, wn = warp >> 1;

    const uint32_t smem_base = (uint32_t)__cvta_generic_to_shared(smd);

    auto load_stage = [&](int s, int kt) {
        const int k0 = kt * 32;
        const uint32_t As = smem_base + s * 32768;
        const uint32_t Bs = As + 16384;
#pragma unroll
        for (int i = 0; i < 4; i++) {
            int lin = i * 256 + tid;
            int row = lin >> 3, ch = lin & 7;
            const bf16* srcA = ((ch & 4) ? Al : Ah) + (size_t)(bm + row) * lda + k0 + (ch & 3) * 8;
            cp16(As + row * 128 + ((ch ^ (row & 7)) * 16), srcA, true);
        }
#pragma unroll
        for (int i = 0; i < 4; i++) {
            int lin = i * 256 + tid;
            int row = lin >> 3, ch = lin & 7;
            bool ok = (bn + row) < N;
            const bf16* srcB = ((ch & 4) ? Bl : Bh) +
                               (ok ? ((size_t)(bn + row) * ldb + k0 + (ch & 3) * 8) : 0);
            cp16(Bs + row * 128 + ((ch ^ (row & 7)) * 16), srcB, ok);
        }
    };

    float acc[4][4][4];
#pragma unroll
    for (int i = 0; i < 4; i++)
#pragma unroll
        for (int j = 0; j < 4; j++)
#pragma unroll
            for (int q = 0; q < 4; q++) acc[i][j][q] = 0.0f;

    const int nk = K / 32;
    if (nk > 0) load_stage(0, 0);
    cp_commit();
    if (nk > 1) load_stage(1, 1);
    cp_commit();

    const int g  = lane >> 3;
    const int lr = lane & 7;
    const int aRow0 = wm * 64 + (g & 1) * 8 + lr;
    const int bRow0 = wn * 32 + (g & 1) * 8 + lr;
    const int chHi  = (g >> 1);

    for (int kt = 0; kt < nk; kt++) {
        cp_wait1();
        __syncthreads();
        const uint32_t As = smem_base + (kt % BK_STAGES) * 32768;
        const uint32_t Bs = As + 16384;

#pragma unroll
        for (int step = 0; step < 2; step++) {
            uint32_t ah[4][4], al[4][4], bh[2][4], bl[2][4];
            const int cH = ((step * 2 + chHi) ^ lr) * 16;
            const int cL = ((4 + step * 2 + chHi) ^ lr) * 16;
#pragma unroll
            for (int mt = 0; mt < 4; mt++) {
                uint32_t rb = As + (uint32_t)(aRow0 + mt * 16) * 128;
                ldsm4(ah[mt], rb + cH);
                ldsm4(al[mt], rb + cL);
            }
#pragma unroll
            for (int p = 0; p < 2; p++) {
                uint32_t rb = Bs + (uint32_t)(bRow0 + p * 16) * 128;
                ldsm4(bh[p], rb + cH);
                ldsm4(bl[p], rb + cL);
            }
#pragma unroll
            for (int nt = 0; nt < 4; nt++) {
                const int p = nt >> 1, o = nt & 1;
                const uint32_t b0h = bh[p][o], b1h = bh[p][o + 2];
                const uint32_t b0l = bl[p][o], b1l = bl[p][o + 2];
#pragma unroll
                for (int mt = 0; mt < 4; mt++) {
                    mma16816(acc[mt][nt], ah[mt], b0h, b1h);
                    mma16816(acc[mt][nt], ah[mt], b0l, b1l);
                    mma16816(acc[mt][nt], al[mt], b0h, b1h);
                }
            }
        }
        __syncthreads();
        if (kt + 2 < nk) load_stage((kt + 2) % BK_STAGES, kt + 2);
        cp_commit();
    }

    const int r_ep = lane >> 2, c_ep = lane & 3;
#pragma unroll
    for (int mt = 0; mt < 4; mt++) {
        const int m0 = bm + wm * 64 + mt * 16 + r_ep;
#pragma unroll
        for (int nt = 0; nt < 4; nt++) {
            const int n0 = bn + wn * 32 + nt * 8 + 2 * c_ep;
#pragma unroll
            for (int half = 0; half < 2; half++) {
                const int m = m0 + half * 8;
#pragma unroll
                for (int q = 0; q < 2; q++) {
                    const int n = n0 + q;
                    if (n < N) {
                        float v = acc[mt][nt][half * 2 + q];
                        if (bp) v += bp[n];
                        if (EPI == 1)      v = geluf(v);
                        else if (EPI == 3) v = softplusf(v);
                        else if (EPI == 4) v += aux[(size_t)(m % auxMod) * ldc + n];
                        else if (EPI == 5) v += aux[(size_t)m * ldc + n];
                        if (OUT != 2) C[(size_t)m * ldc + n] = v;
                        if (OUT != 0) {
                            bf16 h, l; splitf(v, h, l);
                            size_t o = (size_t)m * ldch + n;
                            Ch[o] = h; Ch[planeC + o] = l;
                        }
                    }
                }
            }
        }
    }
}

// ---------------- fp32 -> hi/lo converts ----------------
__global__ void conv_hl_k(const float* __restrict__ src, int ld, int cols, int total,
                          long long plane, bf16* __restrict__ dst)
{
    int i = blockIdx.x * 256 + threadIdx.x;
    if (i >= total) return;
    int r = i / cols, c = i - r * cols;
    float v = src[(size_t)r * ld + c];
    bf16 h, l; splitf(v, h, l);
    dst[i] = h; dst[plane + i] = l;
}
__global__ void conv_hl_t_k(const float* __restrict__ src, int J, int E,
                            long long plane, bf16* __restrict__ dst)
{
    int i = blockIdx.x * 256 + threadIdx.x;
    if (i >= J * E) return;
    int e = i / J, j = i - e * J;
    float v = src[(size_t)j * E + e];
    bf16 h, l; splitf(v, h, l);
    dst[i] = h; dst[plane + i] = l;
}

// ---------------- positional features ----------------
__global__ void pos_hidden_k(const float* __restrict__ w1, const float* __restrict__ b1,
                             bf16* __restrict__ ph)
{
    int idx = blockIdx.x * 256 + threadIdx.x;
    if (idx >= LSEQ * DIM) return;
    int t = idx >> 9;
    int c = idx & 511;
    int y = t >> 5, x = t & 31;
    const float PI = 3.14159265358979323846f;
    float yy = ((y + 0.5f) / 32.0f) * 2.0f - 1.0f;
    float xx = ((x + 0.5f) / 32.0f) * 2.0f - 1.0f;
    float f2 = sinf(PI * yy), f3 = cosf(PI * yy);
    float f4 = sinf(PI * xx), f5 = cosf(PI * xx);
    const float* w = w1 + c * 6;
    float v = b1[c] + yy * w[0] + xx * w[1] + f2 * w[2] + f3 * w[3] + f4 * w[4] + f5 * w[5];
    v = geluf(v);
    bf16 h, l; splitf(v, h, l);
    ph[idx] = h; ph[LSEQ * DIM + idx] = l;
}

// ---------------- LN(tokens) + pos -> hi/lo ----------------
__global__ void ln_add_pos_k(const float* __restrict__ x,
                             const float* __restrict__ g, const float* __restrict__ b,
                             const float* __restrict__ pos, bf16* __restrict__ out)
{
    __shared__ float sh[32];
    const int row = blockIdx.x;
    const int tid = threadIdx.x;
    const float* xr = x + (size_t)row * DIM;
    float v0 = xr[tid], v1 = xr[tid + 256];

    float s = v0 + v1, q = v0 * v0 + v1 * v1;
#pragma unroll
    for (int o = 16; o; o >>= 1) {
        s += __shfl_xor_sync(0xffffffffu, s, o);
        q += __shfl_xor_sync(0xffffffffu, q, o);
    }
    if ((tid & 31) == 0) { sh[tid >> 5] = s; sh[8 + (tid >> 5)] = q; }
    __syncthreads();
    if (tid == 0) {
        float S = 0.f, Q = 0.f;
        for (int i = 0; i < 8; i++) { S += sh[i]; Q += sh[8 + i]; }
        float mu = S * (1.0f / DIM);
        float var = Q * (1.0f / DIM) - mu * mu;
        sh[16] = mu; sh[17] = rsqrtf(var + 1e-5f);
    }
    __syncthreads();
    const float mu = sh[16], rs = sh[17];
    const int t = row & (LSEQ - 1);
    const float* pr = pos + (size_t)t * DIM;
    const long long plane = (long long)ROWS * DIM;
    float r0 = (v0 - mu) * rs * g[tid]       + b[tid]       + pr[tid];
    float r1 = (v1 - mu) * rs * g[tid + 256] + b[tid + 256] + pr[tid + 256];
    bf16 h, l;
    size_t o0 = (size_t)row * DIM + tid;
    splitf(r0, h, l); out[o0] = h; out[plane + o0] = l;
    splitf(r1, h, l); out[o0 + 256] = h; out[plane + o0 + 256] = l;
}

// ---------------- causal conv + SiLU ----------------
__global__ void conv_silu_k(const float* __restrict__ xz,
                            const float* __restrict__ cw, const float* __restrict__ cb,
                            float* __restrict__ xc, bf16* __restrict__ xch)
{
    size_t idx = (size_t)blockIdx.x * 256 + threadIdx.x;
    int d   = (int)(idx & 1023);
    int row = (int)((idx >> 10) & (ROWS - 1));
    int dir = (int)(idx >> 23);
    int t = row & (LSEQ - 1);
    int b = row >> 10;

    float acc = cb[dir * DI + d];
#pragma unroll
    for (int k = 0; k < 4; k++) {
        int off = dir ? (3 - k) : (k - 3);
        int tt = t + off;
        if (tt >= 0 && tt < LSEQ) {
            float v = xz[((size_t)(b * LSEQ + tt)) * 4096 + dir * 2048 + d];
            acc = fmaf(cw[(dir * DI + d) * 4 + k], v, acc);
        }
    }
    float v = siluf(acc);
    xc[idx] = v;
    bf16 h, l; splitf(v, h, l);
    xch[idx] = h; xch[(size_t)2 * ROWS * DI + idx] = l;
}

// ---------------- selective scan ----------------
__global__ void scan_k(const float* __restrict__ dsp, const float* __restrict__ xc,
                       const float* __restrict__ proj, const float* __restrict__ xz,
                       const float* __restrict__ A_log, const float* __restrict__ Dp,
                       bf16* __restrict__ ycat)
{
    const int dir = blockIdx.z;
    const int b   = blockIdx.y;
    const int d   = blockIdx.x * 128 + threadIdx.x;

    float a[DS];
    bool fast = true;
#pragma unroll
    for (int s = 0; s < DS; s++) {
        a[s] = -expf(A_log[((size_t)dir * DI + d) * DS + s]);
        fast = fast && (fabsf(a[s] + (float)(s + 1)) < 1e-4f * (float)(s + 1));
    }
    const float Dv = Dp[dir * DI + d];

    float h[DS];
#pragma unroll
    for (int s = 0; s < DS; s++) h[s] = 0.0f;

    const size_t base_row = (size_t)dir * ROWS + (size_t)b * LSEQ;
    const long long plane = (long long)ROWS * 2048;
    __shared__ float sBC[64][32];

    for (int tc = 0; tc < LSEQ; tc += 64) {
        __syncthreads();
        for (int i = threadIdx.x; i < 64 * 32; i += 128) {
            int step = tc + (i >> 5);
            int c = i & 31;
            int r = dir ? (LSEQ - 1 - step) : step;
            sBC[i >> 5][c] = proj[(base_row + r) * 64 + 32 + c];
        }
        __syncthreads();

        for (int i = 0; i < 64; i++) {
            int step = tc + i;
            int r = dir ? (LSEQ - 1 - step) : step;
            size_t ro = (base_row + r) * (size_t)DI + d;
            float delta = dsp[ro];
            float x     = xc[ro];
            float dx    = delta * x;
            float y = 0.0f;
            float e[DS];
            if (fast) {
                float e1 = __expf(-delta);
                float e2 = e1 * e1, e4 = e2 * e2, e8 = e4 * e4;
                e[0] = e1;        e[1] = e2;        e[2] = e2 * e1;   e[3] = e4;
                e[4] = e4 * e1;   e[5] = e4 * e2;   e[6] = e4 * e[2]; e[7] = e8;
                e[8] = e8 * e1;   e[9] = e8 * e2;   e[10] = e8 * e[2]; e[11] = e8 * e4;
                e[12] = e8 * e[4]; e[13] = e8 * e[5]; e[14] = e8 * e[6]; e[15] = e8 * e8;
            } else {
#pragma unroll
                for (int s = 0; s < DS; s++) e[s] = __expf(delta * a[s]);
            }
#pragma unroll
            for (int s = 0; s < DS; s++) {
                h[s] = fmaf(h[s], e[s], dx * sBC[i][s]);
                y = fmaf(h[s], sBC[i][16 + s], y);
            }
            float z = xz[((size_t)(b * LSEQ + r)) * 4096 + dir * 2048 + DI + d];
            float outv = (y + x * Dv) * siluf(z);
            bf16 hh, ll; splitf(outv, hh, ll);
            size_t oo = ((size_t)(b * LSEQ + r)) * 2048 + dir * DI + d;
            ycat[oo] = hh; ycat[plane + oo] = ll;
        }
    }
}

// ---------------- dual LayerNorm ----------------
__global__ void ln_dual_k(const float* __restrict__ in,
                          const float* __restrict__ g1, const float* __restrict__ b1,
                          const float* __restrict__ g2, const float* __restrict__ b2,
                          float* __restrict__ out1, bf16* __restrict__ out2)
{
    __shared__ float sh[32];
    const int row = blockIdx.x;
    const int tid = threadIdx.x;
    const float* xr = in + (size_t)row * DIM;
    float v0 = xr[tid], v1 = xr[tid + 256];

    float s = v0 + v1, q = v0 * v0 + v1 * v1;
#pragma unroll
    for (int o = 16; o; o >>= 1) {
        s += __shfl_xor_sync(0xffffffffu, s, o);
        q += __shfl_xor_sync(0xffffffffu, q, o);
    }
    if ((tid & 31) == 0) { sh[tid >> 5] = s; sh[8 + (tid >> 5)] = q; }
    __syncthreads();
    if (tid == 0) {
        float S = 0.f, Q = 0.f;
        for (int i = 0; i < 8; i++) { S += sh[i]; Q += sh[8 + i]; }
        float mu = S * (1.0f / DIM);
        float var = Q * (1.0f / DIM) - mu * mu;
        sh[16] = mu; sh[17] = rsqrtf(var + 1e-5f);
    }
    __syncthreads();
    float mu = sh[16], rs = sh[17];
    float x0 = (v0 - mu) * rs * g1[tid]       + b1[tid];
    float x1 = (v1 - mu) * rs * g1[tid + 256] + b1[tid + 256];
    float* o1 = out1 + (size_t)row * DIM;
    o1[tid] = x0; o1[tid + 256] = x1;

    __syncthreads();
    s = x0 + x1; q = x0 * x0 + x1 * x1;
#pragma unroll
    for (int o = 16; o; o >>= 1) {
        s += __shfl_xor_sync(0xffffffffu, s, o);
        q += __shfl_xor_sync(0xffffffffu, q, o);
    }
    if ((tid & 31) == 0) { sh[tid >> 5] = s; sh[8 + (tid >> 5)] = q; }
    __syncthreads();
    if (tid == 0) {
        float S = 0.f, Q = 0.f;
        for (int i = 0; i < 8; i++) { S += sh[i]; Q += sh[8 + i]; }
        float mu2 = S * (1.0f / DIM);
        float var2 = Q * (1.0f / DIM) - mu2 * mu2;
        sh[16] = mu2; sh[17] = rsqrtf(var2 + 1e-5f);
    }
    __syncthreads();
    float mu2 = sh[16], rs2 = sh[17];
    const long long plane = (long long)ROWS * DIM;
    float y0 = (x0 - mu2) * rs2 * g2[tid]       + b2[tid];
    float y1 = (x1 - mu2) * rs2 * g2[tid + 256] + b2[tid + 256];
    bf16 h, l;
    size_t o0 = (size_t)row * DIM + tid;
    splitf(y0, h, l); out2[o0] = h; out2[plane + o0] = l;
    splitf(y1, h, l); out2[o0 + 256] = h; out2[plane + o0 + 256] = l;
}

// ---------------- host launcher ----------------
extern "C" void kernel_launch(void* const* d_in, const int* in_sizes, int n_in,
                              void* d_out, int out_size)
{
    const float* tokens    = (const float*)d_in[0];
    const float* in_g      = (const float*)d_in[3];
    const float* in_b      = (const float*)d_in[4];
    const float* pos_w1    = (const float*)d_in[5];
    const float* pos_b1    = (const float*)d_in[6];
    const float* pos_w2    = (const float*)d_in[7];
    const float* pos_b2    = (const float*)d_in[8];
    const float* m_in_w    = (const float*)d_in[9];
    const float* m_conv_w  = (const float*)d_in[10];
    const float* m_conv_b  = (const float*)d_in[11];
    const float* m_xproj_w = (const float*)d_in[12];
    const float* m_dt_w    = (const float*)d_in[13];
    const float* m_dt_b    = (const float*)d_in[14];
    const float* m_A_log   = (const float*)d_in[15];
    const float* m_D       = (const float*)d_in[16];
    const float* m_out_w   = (const float*)d_in[17];
    const float* mix_w     = (const float*)d_in[18];
    const float* mix_b     = (const float*)d_in[19];
    const float* dn_g      = (const float*)d_in[20];
    const float* dn_b      = (const float*)d_in[21];
    const float* fn_g      = (const float*)d_in[22];
    const float* fn_b      = (const float*)d_in[23];
    const float* ffn_w1    = (const float*)d_in[24];
    const float* ffn_b1    = (const float*)d_in[25];
    const float* ffn_w2    = (const float*)d_in[26];
    const float* ffn_b2    = (const float*)d_in[27];
    float* out = (float*)d_out;

    float *pos, *pos_mix, *xz, *xc, *proj, *dsp, *dmix, *dln;
    bf16 *sin_hl, *posh_hl, *pos_hl, *wpos2, *wpmix, *wmixA, *wTout, *win, *wxp, *wdt, *wf1, *wf2;
    bf16 *xc_hl, *proj_hl, *ycat_hl, *wc_hl, *lnf_hl, *h1_hl;
    cudaGetSymbolAddress((void**)&pos,     g_pos);
    cudaGetSymbolAddress((void**)&pos_mix, g_pos_mix);
    cudaGetSymbolAddress((void**)&xz,      g_xz);
    cudaGetSymbolAddress((void**)&xc,      g_xc);
    cudaGetSymbolAddress((void**)&proj,    g_proj);
    cudaGetSymbolAddress((void**)&dsp,     g_dsp);
    cudaGetSymbolAddress((void**)&dmix,    g_dmix);
    cudaGetSymbolAddress((void**)&dln,     g_dln);
    cudaGetSymbolAddress((void**)&sin_hl,  hl_scan_in);
    cudaGetSymbolAddress((void**)&posh_hl, hl_pos_h);
    cudaGetSymbolAddress((void**)&pos_hl,  hl_pos);
    cudaGetSymbolAddress((void**)&wpos2,   hl_w_pos2);
    cudaGetSymbolAddress((void**)&wpmix,   hl_w_pmix);
    cudaGetSymbolAddress((void**)&wmixA,   hl_w_mixA);
    cudaGetSymbolAddress((void**)&wTout,   hl_wT_out);
    cudaGetSymbolAddress((void**)&win,     hl_w_in);
    cudaGetSymbolAddress((void**)&wxp,     hl_w_xp);
    cudaGetSymbolAddress((void**)&wdt,     hl_w_dt);
    cudaGetSymbolAddress((void**)&wf1,     hl_w_f1);
    cudaGetSymbolAddress((void**)&wf2,     hl_w_f2);
    cudaGetSymbolAddress((void**)&xc_hl,   hl_xc);
    cudaGetSymbolAddress((void**)&proj_hl, hl_proj);
    cudaGetSymbolAddress((void**)&ycat_hl, hl_ycat);
    cudaGetSymbolAddress((void**)&wc_hl,   hl_wc);
    cudaGetSymbolAddress((void**)&lnf_hl,  hl_lnf);
    cudaGetSymbolAddress((void**)&h1_hl,   hl_h1);

    cudaFuncSetAttribute(bgemm<0,0>, cudaFuncAttributeMaxDynamicSharedMemorySize, SMEM_BYTES);
    cudaFuncSetAttribute(bgemm<0,1>, cudaFuncAttributeMaxDynamicSharedMemorySize, SMEM_BYTES);
    cudaFuncSetAttribute(bgemm<0,2>, cudaFuncAttributeMaxDynamicSharedMemorySize, SMEM_BYTES);
    cudaFuncSetAttribute(bgemm<3,0>, cudaFuncAttributeMaxDynamicSharedMemorySize, SMEM_BYTES);
    cudaFuncSetAttribute(bgemm2<0,0>, cudaFuncAttributeMaxDynamicSharedMemorySize, BG2_SMEM);
    cudaFuncSetAttribute(bgemm2<4,0>, cudaFuncAttributeMaxDynamicSharedMemorySize, BG2_SMEM);
    cudaFuncSetAttribute(bgemm2<1,2>, cudaFuncAttributeMaxDynamicSharedMemorySize, BG2_SMEM);
    cudaFuncSetAttribute(bgemm2<5,0>, cudaFuncAttributeMaxDynamicSharedMemorySize, BG2_SMEM);

    // ---- weight converts ----
    conv_hl_k<<<1024, 256>>>(pos_w2,       512, 512, 512*512, 512*512, wpos2);
    conv_hl_k<<<1024, 256>>>(mix_w + 1024, 1536, 512, 512*512, 512*512, wpmix);
    conv_hl_k<<<1024, 256>>>(mix_w,        1536, 512, 512*512, (long long)2*512*512, wmixA);
    conv_hl_k<<<1024, 256>>>(mix_w + 512,  1536, 512, 512*512, (long long)2*512*512, wmixA + 512*512);
    conv_hl_t_k<<<2048, 256>>>(m_out_w,            512, 1024, (long long)2*1024*512, wTout);
    conv_hl_t_k<<<2048, 256>>>(m_out_w + 512*1024, 512, 1024, (long long)2*1024*512, wTout + 1024*512);
    conv_hl_k<<<8192, 256>>>(m_in_w,    512, 512, 4096*512, (long long)4096*512, win);
    conv_hl_k<<<512,  256>>>(m_xproj_w, 1024, 1024, 128*1024, (long long)128*1024, wxp);
    conv_hl_k<<<256,  256>>>(m_dt_w,    32, 32, 2048*32, (long long)2048*32, wdt);
    conv_hl_k<<<2048, 256>>>(ffn_w1,    512, 512, 1024*512, (long long)1024*512, wf1);
    conv_hl_k<<<2048, 256>>>(ffn_w2,    1024, 1024, 512*1024, (long long)512*1024, wf2);

    // ---- pos pipeline (128-tile kernel) ----
    pos_hidden_k<<<2048, 256>>>(pos_w1, pos_b1, posh_hl);
    bgemm<0,1><<<dim3(4,8,1), 256, SMEM_BYTES>>>(
        posh_hl, posh_hl + LSEQ*DIM, 512, 0,  wpos2, wpos2 + 512*512, 512, 0,
        pos, 512, 0,  pos_hl, (long long)LSEQ*DIM, 512, 0,
        pos_b2, 0, nullptr, 1, LSEQ, 512, 512);
    bgemm<0,0><<<dim3(4,8,1), 256, SMEM_BYTES>>>(
        pos_hl, pos_hl + LSEQ*DIM, 512, 0,  wpmix, wpmix + 512*512, 512, 0,
        pos_mix, 512, 0,  nullptr, 0, 0, 0,
        mix_b, 0, nullptr, 1, LSEQ, 512, 512);
    bgemm<0,2><<<dim3(8,4,2), 256, SMEM_BYTES>>>(
        wmixA, wmixA + (long long)2*512*512, 512, (long long)512*512,
        wTout, wTout + (long long)2*1024*512, 512, (long long)1024*512,
        nullptr, 0, 0,
        wc_hl, (long long)512*2048, 2048, 1024,
        nullptr, 0, nullptr, 1, 512, 1024, 512);
    ln_add_pos_k<<<ROWS, 256>>>(tokens, in_g, in_b, pos, sin_hl);

    // xz = scan_in @ in_w^T  (128x256 tile)
    bgemm2<0,0><<<dim3(16,64,1), 256, BG2_SMEM>>>(
        sin_hl, sin_hl + (long long)ROWS*DIM, 512,
        win, win + (long long)4096*512, 512,
        xz, 4096, nullptr, 0, 0,
        nullptr, nullptr, 1, 512);
    conv_silu_k<<<(2*ROWS*DI)/256, 256>>>(xz, m_conv_w, m_conv_b, xc, xc_hl);
    bgemm<0,1><<<dim3(1,64,2), 256, SMEM_BYTES>>>(
        xc_hl, xc_hl + (long long)2*ROWS*DI, 1024, (long long)ROWS*DI,
        wxp, wxp + (long long)128*1024, 1024, (long long)64*1024,
        proj, 64, (long long)ROWS*64,
        proj_hl, (long long)2*ROWS*64, 64, (long long)ROWS*64,
        nullptr, 0, nullptr, 1, ROWS, 64, 1024);
    bgemm<3,0><<<dim3(8,64,2), 256, SMEM_BYTES>>>(
        proj_hl, proj_hl + (long long)2*ROWS*64, 64, (long long)ROWS*64,
        wdt, wdt + (long long)2048*32, 32, (long long)1024*32,
        dsp, 1024, (long long)ROWS*DI, nullptr, 0, 0, 0,
        m_dt_b, 1024, nullptr, 1, ROWS, 1024, 32);
    scan_k<<<dim3(DI/128, BATCH, 2), 128>>>(dsp, xc, proj, xz, m_A_log, m_D, ycat_hl);
    // dmix = ycat @ Wc^T + pos_mix (128x256 tile)
    bgemm2<4,0><<<dim3(2,64,1), 256, BG2_SMEM>>>(
        ycat_hl, ycat_hl + (long long)ROWS*2048, 2048,
        wc_hl, wc_hl + (long long)512*2048, 2048,
        dmix, 512, nullptr, 0, 0,
        nullptr, pos_mix, LSEQ, 2048);
    ln_dual_k<<<ROWS, 256>>>(dmix, dn_g, dn_b, fn_g, fn_b, dln, lnf_hl);
    // h1 = gelu(lnf @ ffn_w1^T + b1) -> hi/lo (128x256 tile)
    bgemm2<1,2><<<dim3(4,64,1), 256, BG2_SMEM>>>(
        lnf_hl, lnf_hl + (long long)ROWS*DIM, 512,
        wf1, wf1 + (long long)1024*512, 512,
        nullptr, 1024, h1_hl, (long long)ROWS*HID, 1024,
        ffn_b1, nullptr, 1, 512);
    // out = dln + h1 @ ffn_w2^T + b2 (128x256 tile)
    bgemm2<5,0><<<dim3(2,64,1), 256, BG2_SMEM>>>(
        h1_hl, h1_hl + (long long)ROWS*HID, 1024,
        wf2, wf2 + (long long)512*1024, 1024,
        out, 512, nullptr, 0, 0,
        ffn_b2, dln, 1, 1024);

    (void)in_sizes; (void)n_in; (void)out_size;
}

// round 7
// speedup vs baseline: 1.1871x; 1.1871x over previous
#include <cuda_runtime.h>
#include <cuda_bf16.h>
#include <cstdint>
#include <math.h>

#define BATCH 8
#define LSEQ  1024
#define DIM   512
#define DI    1024
#define DS    16
#define HID   1024
#define ROWS  (BATCH*LSEQ)    // 8192

typedef __nv_bfloat16 bf16;

// ---------------- fp32 scratch ----------------
__device__ float g_pos    [LSEQ*DIM];
__device__ float g_pos_mix[LSEQ*DIM];
__device__ float g_xz     [ROWS*4096];
__device__ float g_xc     [2*ROWS*DI];
__device__ float g_proj   [2*ROWS*64];
__device__ float g_dsp    [2*ROWS*DI];
__device__ float g_dmix   [ROWS*DIM];
__device__ float g_dln    [ROWS*DIM];

// ---------------- bf16 hi/lo scratch ----------------
__device__ __align__(16) bf16 hl_scan_in[2*ROWS*DIM];
__device__ __align__(16) bf16 hl_pos_h  [2*LSEQ*DIM];
__device__ __align__(16) bf16 hl_pos    [2*LSEQ*DIM];
__device__ __align__(16) bf16 hl_w_pos2 [2*DIM*DIM];
__device__ __align__(16) bf16 hl_w_pmix [2*DIM*DIM];
__device__ __align__(16) bf16 hl_w_mixA [2*2*DIM*DIM];
__device__ __align__(16) bf16 hl_wT_out [2*2*DI*DIM];
__device__ __align__(16) bf16 hl_w_in   [2*4096*DIM];
__device__ __align__(16) bf16 hl_w_xp   [2*2*64*DI];
__device__ __align__(16) bf16 hl_w_dt   [2*2*DI*32];
__device__ __align__(16) bf16 hl_w_f1   [2*HID*DIM];
__device__ __align__(16) bf16 hl_w_f2   [2*DIM*HID];
__device__ __align__(16) bf16 hl_xc     [2*2*ROWS*DI];
__device__ __align__(16) bf16 hl_proj   [2*2*ROWS*64];
__device__ __align__(16) bf16 hl_ycat   [2*ROWS*2048];
__device__ __align__(16) bf16 hl_wc     [2*DIM*2048];
__device__ __align__(16) bf16 hl_lnf    [2*ROWS*DIM];
__device__ __align__(16) bf16 hl_h1     [2*ROWS*HID];

// ---------------- math helpers ----------------
__device__ __forceinline__ float geluf(float x) {
    return 0.5f * x * (1.0f + erff(x * 0.70710678118654752440f));
}
__device__ __forceinline__ float siluf(float x) { return x / (1.0f + __expf(-x)); }
__device__ __forceinline__ float softplusf(float x) { return (x > 20.0f) ? x : log1pf(__expf(x)); }
__device__ __forceinline__ void splitf(float v, bf16& h, bf16& l) {
    h = __float2bfloat16(v);
    l = __float2bfloat16(v - __bfloat162float(h));
}

// ---------------- PTX helpers ----------------
__device__ __forceinline__ void mma16816(float* d, const uint32_t* a, uint32_t b0, uint32_t b1) {
    asm volatile(
        "mma.sync.aligned.m16n8k16.row.col.f32.bf16.bf16.f32 "
        "{%0,%1,%2,%3},{%4,%5,%6,%7},{%8,%9},{%0,%1,%2,%3};\n"
        : "+f"(d[0]), "+f"(d[1]), "+f"(d[2]), "+f"(d[3])
        : "r"(a[0]), "r"(a[1]), "r"(a[2]), "r"(a[3]), "r"(b0), "r"(b1));
}
__device__ __forceinline__ void ldsm4(uint32_t* r, uint32_t addr) {
    asm volatile("ldmatrix.sync.aligned.m8n8.x4.shared.b16 {%0,%1,%2,%3}, [%4];\n"
                 : "=r"(r[0]), "=r"(r[1]), "=r"(r[2]), "=r"(r[3]) : "r"(addr));
}
__device__ __forceinline__ void cp16(uint32_t dst, const void* src, bool pred) {
    int sz = pred ? 16 : 0;
    asm volatile("cp.async.cg.shared.global [%0], [%1], 16, %2;\n"
                 :: "r"(dst), "l"(src), "r"(sz) : "memory");
}
__device__ __forceinline__ void cp_commit() { asm volatile("cp.async.commit_group;\n" ::: "memory"); }
__device__ __forceinline__ void cp_wait1()  { asm volatile("cp.async.wait_group 1;\n" ::: "memory"); }

// ---------------- mma.sync GEMM (pre-split bf16 hi/lo, 3-term) — exact R3 config ----------------
// C[m,n] = sum_k A[m,k]*B[n,k];  A=(M,K), B=(N,K), hi/lo planes.
// EPI: 0 none, 1 gelu, 3 softplus, 4 +aux[(m%auxMod)*ldc+n], 5 +aux[m*ldc+n]
// OUT: 0 fp32 only, 1 fp32 + hi/lo, 2 hi/lo only
#define BK_STAGES 3
#define SMEM_BYTES (BK_STAGES*32768)

template<int EPI, int OUT>
__global__ void __launch_bounds__(256)
bgemm(const bf16* __restrict__ Ah, const bf16* __restrict__ Al, int lda, long long sA,
      const bf16* __restrict__ Bh, const bf16* __restrict__ Bl, int ldb, long long sB,
      float* __restrict__ C, int ldc, long long sC,
      bf16* __restrict__ Ch, long long planeC, int ldch, long long sCh,
      const float* __restrict__ bias, long long sBias,
      const float* __restrict__ aux, int auxMod,
      int M, int N, int K)
{
    extern __shared__ char smd[];
    const int zi = blockIdx.z;
    Ah += (size_t)zi * sA; Al += (size_t)zi * sA;
    Bh += (size_t)zi * sB; Bl += (size_t)zi * sB;
    if (OUT != 2) C += (size_t)zi * sC;
    if (OUT != 0) Ch += (size_t)zi * sCh;
    const float* bp = bias ? (bias + (size_t)zi * sBias) : nullptr;

    const int bm = blockIdx.y * 128;
    const int bn = blockIdx.x * 128;
    const int tid = threadIdx.x, lane = tid & 31, warp = tid >> 5;
    const int wm = warp & 1, wn = warp >> 1;

    const uint32_t smem_base = (uint32_t)__cvta_generic_to_shared(smd);

    auto load_stage = [&](int s, int kt) {
        const int k0 = kt * 32;
        const uint32_t As = smem_base + s * 32768;
        const uint32_t Bs = As + 16384;
#pragma unroll
        for (int i = 0; i < 4; i++) {
            int lin = i * 256 + tid;
            int row = lin >> 3, ch = lin & 7;
            const bf16* srcA = ((ch & 4) ? Al : Ah) + (size_t)(bm + row) * lda + k0 + (ch & 3) * 8;
            cp16(As + row * 128 + ((ch ^ (row & 7)) * 16), srcA, true);
        }
#pragma unroll
        for (int i = 0; i < 4; i++) {
            int lin = i * 256 + tid;
            int row = lin >> 3, ch = lin & 7;
            bool ok = (bn + row) < N;
            const bf16* srcB = ((ch & 4) ? Bl : Bh) +
                               (ok ? ((size_t)(bn + row) * ldb + k0 + (ch & 3) * 8) : 0);
            cp16(Bs + row * 128 + ((ch ^ (row & 7)) * 16), srcB, ok);
        }
    };

    float acc[4][4][4];
#pragma unroll
    for (int i = 0; i < 4; i++)
#pragma unroll
        for (int j = 0; j < 4; j++)
#pragma unroll
            for (int q = 0; q < 4; q++) acc[i][j][q] = 0.0f;

    const int nk = K / 32;
    if (nk > 0) load_stage(0, 0);
    cp_commit();
    if (nk > 1) load_stage(1, 1);
    cp_commit();

    const int g  = lane >> 3;
    const int lr = lane & 7;
    const int aRow0 = wm * 64 + (g & 1) * 8 + lr;
    const int bRow0 = wn * 32 + (g & 1) * 8 + lr;
    const int chHi  = (g >> 1);

    for (int kt = 0; kt < nk; kt++) {
        cp_wait1();
        __syncthreads();
        const uint32_t As = smem_base + (kt % BK_STAGES) * 32768;
        const uint32_t Bs = As + 16384;

#pragma unroll
        for (int step = 0; step < 2; step++) {
            uint32_t ah[4][4], al[4][4], bh[2][4], bl[2][4];
            const int cH = ((step * 2 + chHi) ^ lr) * 16;
            const int cL = ((4 + step * 2 + chHi) ^ lr) * 16;
#pragma unroll
            for (int mt = 0; mt < 4; mt++) {
                uint32_t rb = As + (uint32_t)(aRow0 + mt * 16) * 128;
                ldsm4(ah[mt], rb + cH);
                ldsm4(al[mt], rb + cL);
            }
#pragma unroll
            for (int p = 0; p < 2; p++) {
                uint32_t rb = Bs + (uint32_t)(bRow0 + p * 16) * 128;
                ldsm4(bh[p], rb + cH);
                ldsm4(bl[p], rb + cL);
            }
#pragma unroll
            for (int nt = 0; nt < 4; nt++) {
                const int p = nt >> 1, o = nt & 1;
                const uint32_t b0h = bh[p][o], b1h = bh[p][o + 2];
                const uint32_t b0l = bl[p][o], b1l = bl[p][o + 2];
#pragma unroll
                for (int mt = 0; mt < 4; mt++) {
                    mma16816(acc[mt][nt], ah[mt], b0h, b1h);
                    mma16816(acc[mt][nt], ah[mt], b0l, b1l);
                    mma16816(acc[mt][nt], al[mt], b0h, b1h);
                }
            }
        }
        __syncthreads();
        if (kt + 2 < nk) load_stage((kt + 2) % BK_STAGES, kt + 2);
        cp_commit();
    }

    const int r_ep = lane >> 2, c_ep = lane & 3;
#pragma unroll
    for (int mt = 0; mt < 4; mt++) {
        const int m0 = bm + wm * 64 + mt * 16 + r_ep;
#pragma unroll
        for (int nt = 0; nt < 4; nt++) {
            const int n0 = bn + wn * 32 + nt * 8 + 2 * c_ep;
#pragma unroll
            for (int half = 0; half < 2; half++) {
                const int m = m0 + half * 8;
#pragma unroll
                for (int q = 0; q < 2; q++) {
                    const int n = n0 + q;
                    if (n < N) {
                        float v = acc[mt][nt][half * 2 + q];
                        if (bp) v += bp[n];
                        if (EPI == 1)      v = geluf(v);
                        else if (EPI == 3) v = softplusf(v);
                        else if (EPI == 4) v += aux[(size_t)(m % auxMod) * ldc + n];
                        else if (EPI == 5) v += aux[(size_t)m * ldc + n];
                        if (OUT != 2) C[(size_t)m * ldc + n] = v;
                        if (OUT != 0) {
                            bf16 h, l; splitf(v, h, l);
                            size_t o = (size_t)m * ldch + n;
                            Ch[o] = h; Ch[planeC + o] = l;
                        }
                    }
                }
            }
        }
    }
}

// ---------------- fp32 -> hi/lo converts ----------------
__global__ void conv_hl_k(const float* __restrict__ src, int ld, int cols, int total,
                          long long plane, bf16* __restrict__ dst)
{
    int i = blockIdx.x * 256 + threadIdx.x;
    if (i >= total) return;
    int r = i / cols, c = i - r * cols;
    float v = src[(size_t)r * ld + c];
    bf16 h, l; splitf(v, h, l);
    dst[i] = h; dst[plane + i] = l;
}
__global__ void conv_hl_t_k(const float* __restrict__ src, int J, int E,
                            long long plane, bf16* __restrict__ dst)
{
    int i = blockIdx.x * 256 + threadIdx.x;
    if (i >= J * E) return;
    int e = i / J, j = i - e * J;
    float v = src[(size_t)j * E + e];
    bf16 h, l; splitf(v, h, l);
    dst[i] = h; dst[plane + i] = l;
}

// ---------------- positional features ----------------
__global__ void pos_hidden_k(const float* __restrict__ w1, const float* __restrict__ b1,
                             bf16* __restrict__ ph)
{
    int idx = blockIdx.x * 256 + threadIdx.x;
    if (idx >= LSEQ * DIM) return;
    int t = idx >> 9;
    int c = idx & 511;
    int y = t >> 5, x = t & 31;
    const float PI = 3.14159265358979323846f;
    float yy = ((y + 0.5f) / 32.0f) * 2.0f - 1.0f;
    float xx = ((x + 0.5f) / 32.0f) * 2.0f - 1.0f;
    float f2 = sinf(PI * yy), f3 = cosf(PI * yy);
    float f4 = sinf(PI * xx), f5 = cosf(PI * xx);
    const float* w = w1 + c * 6;
    float v = b1[c] + yy * w[0] + xx * w[1] + f2 * w[2] + f3 * w[3] + f4 * w[4] + f5 * w[5];
    v = geluf(v);
    bf16 h, l; splitf(v, h, l);
    ph[idx] = h; ph[LSEQ * DIM + idx] = l;
}

// ---------------- LN(tokens) + pos -> hi/lo ----------------
__global__ void ln_add_pos_k(const float* __restrict__ x,
                             const float* __restrict__ g, const float* __restrict__ b,
                             const float* __restrict__ pos, bf16* __restrict__ out)
{
    __shared__ float sh[32];
    const int row = blockIdx.x;
    const int tid = threadIdx.x;
    const float* xr = x + (size_t)row * DIM;
    float v0 = xr[tid], v1 = xr[tid + 256];

    float s = v0 + v1, q = v0 * v0 + v1 * v1;
#pragma unroll
    for (int o = 16; o; o >>= 1) {
        s += __shfl_xor_sync(0xffffffffu, s, o);
        q += __shfl_xor_sync(0xffffffffu, q, o);
    }
    if ((tid & 31) == 0) { sh[tid >> 5] = s; sh[8 + (tid >> 5)] = q; }
    __syncthreads();
    if (tid == 0) {
        float S = 0.f, Q = 0.f;
        for (int i = 0; i < 8; i++) { S += sh[i]; Q += sh[8 + i]; }
        float mu = S * (1.0f / DIM);
        float var = Q * (1.0f / DIM) - mu * mu;
        sh[16] = mu; sh[17] = rsqrtf(var + 1e-5f);
    }
    __syncthreads();
    const float mu = sh[16], rs = sh[17];
    const int t = row & (LSEQ - 1);
    const float* pr = pos + (size_t)t * DIM;
    const long long plane = (long long)ROWS * DIM;
    float r0 = (v0 - mu) * rs * g[tid]       + b[tid]       + pr[tid];
    float r1 = (v1 - mu) * rs * g[tid + 256] + b[tid + 256] + pr[tid + 256];
    bf16 h, l;
    size_t o0 = (size_t)row * DIM + tid;
    splitf(r0, h, l); out[o0] = h; out[plane + o0] = l;
    splitf(r1, h, l); out[o0 + 256] = h; out[plane + o0 + 256] = l;
}

// ---------------- causal conv + SiLU ----------------
__global__ void conv_silu_k(const float* __restrict__ xz,
                            const float* __restrict__ cw, const float* __restrict__ cb,
                            float* __restrict__ xc, bf16* __restrict__ xch)
{
    size_t idx = (size_t)blockIdx.x * 256 + threadIdx.x;
    int d   = (int)(idx & 1023);
    int row = (int)((idx >> 10) & (ROWS - 1));
    int dir = (int)(idx >> 23);
    int t = row & (LSEQ - 1);
    int b = row >> 10;

    float acc = cb[dir * DI + d];
#pragma unroll
    for (int k = 0; k < 4; k++) {
        int off = dir ? (3 - k) : (k - 3);
        int tt = t + off;
        if (tt >= 0 && tt < LSEQ) {
            float v = xz[((size_t)(b * LSEQ + tt)) * 4096 + dir * 2048 + d];
            acc = fmaf(cw[(dir * DI + d) * 4 + k], v, acc);
        }
    }
    float v = siluf(acc);
    xc[idx] = v;
    bf16 h, l; splitf(v, h, l);
    xch[idx] = h; xch[(size_t)2 * ROWS * DI + idx] = l;
}

// ---------------- selective scan (register-lean exp fast-path) ----------------
__global__ void scan_k(const float* __restrict__ dsp, const float* __restrict__ xc,
                       const float* __restrict__ proj, const float* __restrict__ xz,
                       const float* __restrict__ A_log, const float* __restrict__ Dp,
                       bf16* __restrict__ ycat)
{
    const int dir = blockIdx.z;
    const int b   = blockIdx.y;
    const int d   = blockIdx.x * 128 + threadIdx.x;

    float a[DS];
    bool fast = true;
#pragma unroll
    for (int s = 0; s < DS; s++) {
        a[s] = -expf(A_log[((size_t)dir * DI + d) * DS + s]);
        fast = fast && (fabsf(a[s] + (float)(s + 1)) < 1e-4f * (float)(s + 1));
    }
    const float Dv = Dp[dir * DI + d];

    float h[DS];
#pragma unroll
    for (int s = 0; s < DS; s++) h[s] = 0.0f;

    const size_t base_row = (size_t)dir * ROWS + (size_t)b * LSEQ;
    const long long plane = (long long)ROWS * 2048;
    __shared__ float sBC[64][32];

    for (int tc = 0; tc < LSEQ; tc += 64) {
        __syncthreads();
        for (int i = threadIdx.x; i < 64 * 32; i += 128) {
            int step = tc + (i >> 5);
            int c = i & 31;
            int r = dir ? (LSEQ - 1 - step) : step;
            sBC[i >> 5][c] = proj[(base_row + r) * 64 + 32 + c];
        }
        __syncthreads();

        if (fast) {
            for (int i = 0; i < 64; i++) {
                int step = tc + i;
                int r = dir ? (LSEQ - 1 - step) : step;
                size_t ro = (base_row + r) * (size_t)DI + d;
                float delta = dsp[ro];
                float x     = xc[ro];
                float dx    = delta * x;
                float y = 0.0f;
                // a[s] = -(s+1): e[s] = e1^(s+1) via running product — 1 MUFU/step, no array
                float e1 = __expf(-delta);
                float ep = e1;
#pragma unroll
                for (int s = 0; s < DS; s++) {
                    h[s] = fmaf(h[s], ep, dx * sBC[i][s]);
                    y = fmaf(h[s], sBC[i][16 + s], y);
                    ep *= e1;
                }
                float z = xz[((size_t)(b * LSEQ + r)) * 4096 + dir * 2048 + DI + d];
                float outv = (y + x * Dv) * siluf(z);
                bf16 hh, ll; splitf(outv, hh, ll);
                size_t oo = ((size_t)(b * LSEQ + r)) * 2048 + dir * DI + d;
                ycat[oo] = hh; ycat[plane + oo] = ll;
            }
        } else {
            for (int i = 0; i < 64; i++) {
                int step = tc + i;
                int r = dir ? (LSEQ - 1 - step) : step;
                size_t ro = (base_row + r) * (size_t)DI + d;
                float delta = dsp[ro];
                float x     = xc[ro];
                float dx    = delta * x;
                float y = 0.0f;
#pragma unroll
                for (int s = 0; s < DS; s++) {
                    float e = __expf(delta * a[s]);
                    h[s] = fmaf(h[s], e, dx * sBC[i][s]);
                    y = fmaf(h[s], sBC[i][16 + s], y);
                }
                float z = xz[((size_t)(b * LSEQ + r)) * 4096 + dir * 2048 + DI + d];
                float outv = (y + x * Dv) * siluf(z);
                bf16 hh, ll; splitf(outv, hh, ll);
                size_t oo = ((size_t)(b * LSEQ + r)) * 2048 + dir * DI + d;
                ycat[oo] = hh; ycat[plane + oo] = ll;
            }
        }
    }
}

// ---------------- dual LayerNorm ----------------
__global__ void ln_dual_k(const float* __restrict__ in,
                          const float* __restrict__ g1, const float* __restrict__ b1,
                          const float* __restrict__ g2, const float* __restrict__ b2,
                          float* __restrict__ out1, bf16* __restrict__ out2)
{
    __shared__ float sh[32];
    const int row = blockIdx.x;
    const int tid = threadIdx.x;
    const float* xr = in + (size_t)row * DIM;
    float v0 = xr[tid], v1 = xr[tid + 256];

    float s = v0 + v1, q = v0 * v0 + v1 * v1;
#pragma unroll
    for (int o = 16; o; o >>= 1) {
        s += __shfl_xor_sync(0xffffffffu, s, o);
        q += __shfl_xor_sync(0xffffffffu, q, o);
    }
    if ((tid & 31) == 0) { sh[tid >> 5] = s; sh[8 + (tid >> 5)] = q; }
    __syncthreads();
    if (tid == 0) {
        float S = 0.f, Q = 0.f;
        for (int i = 0; i < 8; i++) { S += sh[i]; Q += sh[8 + i]; }
        float mu = S * (1.0f / DIM);
        float var = Q * (1.0f / DIM) - mu * mu;
        sh[16] = mu; sh[17] = rsqrtf(var + 1e-5f);
    }
    __syncthreads();
    float mu = sh[16], rs = sh[17];
    float x0 = (v0 - mu) * rs * g1[tid]       + b1[tid];
    float x1 = (v1 - mu) * rs * g1[tid + 256] + b1[tid + 256];
    float* o1 = out1 + (size_t)row * DIM;
    o1[tid] = x0; o1[tid + 256] = x1;

    __syncthreads();
    s = x0 + x1; q = x0 * x0 + x1 * x1;
#pragma unroll
    for (int o = 16; o; o >>= 1) {
        s += __shfl_xor_sync(0xffffffffu, s, o);
        q += __shfl_xor_sync(0xffffffffu, q, o);
    }
    if ((tid & 31) == 0) { sh[tid >> 5] = s; sh[8 + (tid >> 5)] = q; }
    __syncthreads();
    if (tid == 0) {
        float S = 0.f, Q = 0.f;
        for (int i = 0; i < 8; i++) { S += sh[i]; Q += sh[8 + i]; }
        float mu2 = S * (1.0f / DIM);
        float var2 = Q * (1.0f / DIM) - mu2 * mu2;
        sh[16] = mu2; sh[17] = rsqrtf(var2 + 1e-5f);
    }
    __syncthreads();
    float mu2 = sh[16], rs2 = sh[17];
    const long long plane = (long long)ROWS * DIM;
    float y0 = (x0 - mu2) * rs2 * g2[tid]       + b2[tid];
    float y1 = (x1 - mu2) * rs2 * g2[tid + 256] + b2[tid + 256];
    bf16 h, l;
    size_t o0 = (size_t)row * DIM + tid;
    splitf(y0, h, l); out2[o0] = h; out2[plane + o0] = l;
    splitf(y1, h, l); out2[o0 + 256] = h; out2[plane + o0 + 256] = l;
}

// ---------------- host launcher ----------------
extern "C" void kernel_launch(void* const* d_in, const int* in_sizes, int n_in,
                              void* d_out, int out_size)
{
    const float* tokens    = (const float*)d_in[0];
    const float* in_g      = (const float*)d_in[3];
    const float* in_b      = (const float*)d_in[4];
    const float* pos_w1    = (const float*)d_in[5];
    const float* pos_b1    = (const float*)d_in[6];
    const float* pos_w2    = (const float*)d_in[7];
    const float* pos_b2    = (const float*)d_in[8];
    const float* m_in_w    = (const float*)d_in[9];
    const float* m_conv_w  = (const float*)d_in[10];
    const float* m_conv_b  = (const float*)d_in[11];
    const float* m_xproj_w = (const float*)d_in[12];
    const float* m_dt_w    = (const float*)d_in[13];
    const float* m_dt_b    = (const float*)d_in[14];
    const float* m_A_log   = (const float*)d_in[15];
    const float* m_D       = (const float*)d_in[16];
    const float* m_out_w   = (const float*)d_in[17];
    const float* mix_w     = (const float*)d_in[18];
    const float* mix_b     = (const float*)d_in[19];
    const float* dn_g      = (const float*)d_in[20];
    const float* dn_b      = (const float*)d_in[21];
    const float* fn_g      = (const float*)d_in[22];
    const float* fn_b      = (const float*)d_in[23];
    const float* ffn_w1    = (const float*)d_in[24];
    const float* ffn_b1    = (const float*)d_in[25];
    const float* ffn_w2    = (const float*)d_in[26];
    const float* ffn_b2    = (const float*)d_in[27];
    float* out = (float*)d_out;

    float *pos, *pos_mix, *xz, *xc, *proj, *dsp, *dmix, *dln;
    bf16 *sin_hl, *posh_hl, *pos_hl, *wpos2, *wpmix, *wmixA, *wTout, *win, *wxp, *wdt, *wf1, *wf2;
    bf16 *xc_hl, *proj_hl, *ycat_hl, *wc_hl, *lnf_hl, *h1_hl;
    cudaGetSymbolAddress((void**)&pos,     g_pos);
    cudaGetSymbolAddress((void**)&pos_mix, g_pos_mix);
    cudaGetSymbolAddress((void**)&xz,      g_xz);
    cudaGetSymbolAddress((void**)&xc,      g_xc);
    cudaGetSymbolAddress((void**)&proj,    g_proj);
    cudaGetSymbolAddress((void**)&dsp,     g_dsp);
    cudaGetSymbolAddress((void**)&dmix,    g_dmix);
    cudaGetSymbolAddress((void**)&dln,     g_dln);
    cudaGetSymbolAddress((void**)&sin_hl,  hl_scan_in);
    cudaGetSymbolAddress((void**)&posh_hl, hl_pos_h);
    cudaGetSymbolAddress((void**)&pos_hl,  hl_pos);
    cudaGetSymbolAddress((void**)&wpos2,   hl_w_pos2);
    cudaGetSymbolAddress((void**)&wpmix,   hl_w_pmix);
    cudaGetSymbolAddress((void**)&wmixA,   hl_w_mixA);
    cudaGetSymbolAddress((void**)&wTout,   hl_wT_out);
    cudaGetSymbolAddress((void**)&win,     hl_w_in);
    cudaGetSymbolAddress((void**)&wxp,     hl_w_xp);
    cudaGetSymbolAddress((void**)&wdt,     hl_w_dt);
    cudaGetSymbolAddress((void**)&wf1,     hl_w_f1);
    cudaGetSymbolAddress((void**)&wf2,     hl_w_f2);
    cudaGetSymbolAddress((void**)&xc_hl,   hl_xc);
    cudaGetSymbolAddress((void**)&proj_hl, hl_proj);
    cudaGetSymbolAddress((void**)&ycat_hl, hl_ycat);
    cudaGetSymbolAddress((void**)&wc_hl,   hl_wc);
    cudaGetSymbolAddress((void**)&lnf_hl,  hl_lnf);
    cudaGetSymbolAddress((void**)&h1_hl,   hl_h1);

    cudaFuncSetAttribute(bgemm<0,0>, cudaFuncAttributeMaxDynamicSharedMemorySize, SMEM_BYTES);
    cudaFuncSetAttribute(bgemm<0,1>, cudaFuncAttributeMaxDynamicSharedMemorySize, SMEM_BYTES);
    cudaFuncSetAttribute(bgemm<0,2>, cudaFuncAttributeMaxDynamicSharedMemorySize, SMEM_BYTES);
    cudaFuncSetAttribute(bgemm<3,0>, cudaFuncAttributeMaxDynamicSharedMemorySize, SMEM_BYTES);
    cudaFuncSetAttribute(bgemm<4,0>, cudaFuncAttributeMaxDynamicSharedMemorySize, SMEM_BYTES);
    cudaFuncSetAttribute(bgemm<1,2>, cudaFuncAttributeMaxDynamicSharedMemorySize, SMEM_BYTES);
    cudaFuncSetAttribute(bgemm<5,0>, cudaFuncAttributeMaxDynamicSharedMemorySize, SMEM_BYTES);

    // ---- weight converts ----
    conv_hl_k<<<1024, 256>>>(pos_w2,       512, 512, 512*512, 512*512, wpos2);
    conv_hl_k<<<1024, 256>>>(mix_w + 1024, 1536, 512, 512*512, 512*512, wpmix);
    conv_hl_k<<<1024, 256>>>(mix_w,        1536, 512, 512*512, (long long)2*512*512, wmixA);
    conv_hl_k<<<1024, 256>>>(mix_w + 512,  1536, 512, 512*512, (long long)2*512*512, wmixA + 512*512);
    conv_hl_t_k<<<2048, 256>>>(m_out_w,            512, 1024, (long long)2*1024*512, wTout);
    conv_hl_t_k<<<2048, 256>>>(m_out_w + 512*1024, 512, 1024, (long long)2*1024*512, wTout + 1024*512);
    conv_hl_k<<<8192, 256>>>(m_in_w,    512, 512, 4096*512, (long long)4096*512, win);
    conv_hl_k<<<512,  256>>>(m_xproj_w, 1024, 1024, 128*1024, (long long)128*1024, wxp);
    conv_hl_k<<<256,  256>>>(m_dt_w,    32, 32, 2048*32, (long long)2048*32, wdt);
    conv_hl_k<<<2048, 256>>>(ffn_w1,    512, 512, 1024*512, (long long)1024*512, wf1);
    conv_hl_k<<<2048, 256>>>(ffn_w2,    1024, 1024, 512*1024, (long long)512*1024, wf2);

    // ---- pos pipeline ----
    pos_hidden_k<<<2048, 256>>>(pos_w1, pos_b1, posh_hl);
    bgemm<0,1><<<dim3(4,8,1), 256, SMEM_BYTES>>>(
        posh_hl, posh_hl + LSEQ*DIM, 512, 0,  wpos2, wpos2 + 512*512, 512, 0,
        pos, 512, 0,  pos_hl, (long long)LSEQ*DIM, 512, 0,
        pos_b2, 0, nullptr, 1, LSEQ, 512, 512);
    bgemm<0,0><<<dim3(4,8,1), 256, SMEM_BYTES>>>(
        pos_hl, pos_hl + LSEQ*DIM, 512, 0,  wpmix, wpmix + 512*512, 512, 0,
        pos_mix, 512, 0,  nullptr, 0, 0, 0,
        mix_b, 0, nullptr, 1, LSEQ, 512, 512);
    bgemm<0,2><<<dim3(8,4,2), 256, SMEM_BYTES>>>(
        wmixA, wmixA + (long long)2*512*512, 512, (long long)512*512,
        wTout, wTout + (long long)2*1024*512, 512, (long long)1024*512,
        nullptr, 0, 0,
        wc_hl, (long long)512*2048, 2048, 1024,
        nullptr, 0, nullptr, 1, 512, 1024, 512);
    ln_add_pos_k<<<ROWS, 256>>>(tokens, in_g, in_b, pos, sin_hl);

    // xz = scan_in @ in_w^T (fused dirs, N=4096)
    bgemm<0,0><<<dim3(32,64,1), 256, SMEM_BYTES>>>(
        sin_hl, sin_hl + (long long)ROWS*DIM, 512, 0,
        win, win + (long long)4096*512, 512, 0,
        xz, 4096, 0, nullptr, 0, 0, 0,
        nullptr, 0, nullptr, 1, ROWS, 4096, 512);
    conv_silu_k<<<(2*ROWS*DI)/256, 256>>>(xz, m_conv_w, m_conv_b, xc, xc_hl);
    bgemm<0,1><<<dim3(1,64,2), 256, SMEM_BYTES>>>(
        xc_hl, xc_hl + (long long)2*ROWS*DI, 1024, (long long)ROWS*DI,
        wxp, wxp + (long long)128*1024, 1024, (long long)64*1024,
        proj, 64, (long long)ROWS*64,
        proj_hl, (long long)2*ROWS*64, 64, (long long)ROWS*64,
        nullptr, 0, nullptr, 1, ROWS, 64, 1024);
    bgemm<3,0><<<dim3(8,64,2), 256, SMEM_BYTES>>>(
        proj_hl, proj_hl + (long long)2*ROWS*64, 64, (long long)ROWS*64,
        wdt, wdt + (long long)2048*32, 32, (long long)1024*32,
        dsp, 1024, (long long)ROWS*DI, nullptr, 0, 0, 0,
        m_dt_b, 1024, nullptr, 1, ROWS, 1024, 32);
    scan_k<<<dim3(DI/128, BATCH, 2), 128>>>(dsp, xc, proj, xz, m_A_log, m_D, ycat_hl);
    bgemm<4,0><<<dim3(4,64,1), 256, SMEM_BYTES>>>(
        ycat_hl, ycat_hl + (long long)ROWS*2048, 2048, 0,
        wc_hl, wc_hl + (long long)512*2048, 2048, 0,
        dmix, 512, 0, nullptr, 0, 0, 0,
        nullptr, 0, pos_mix, LSEQ, ROWS, 512, 2048);
    ln_dual_k<<<ROWS, 256>>>(dmix, dn_g, dn_b, fn_g, fn_b, dln, lnf_hl);
    bgemm<1,2><<<dim3(8,64,1), 256, SMEM_BYTES>>>(
        lnf_hl, lnf_hl + (long long)ROWS*DIM, 512, 0,
        wf1, wf1 + (long long)1024*512, 512, 0,
        nullptr, 1024, 0,
        h1_hl, (long long)ROWS*HID, 1024, 0,
        ffn_b1, 0, nullptr, 1, ROWS, 1024, 512);
    bgemm<5,0><<<dim3(4,64,1), 256, SMEM_BYTES>>>(
        h1_hl, h1_hl + (long long)ROWS*HID, 1024, 0,
        wf2, wf2 + (long long)512*1024, 1024, 0,
        out, 512, 0, nullptr, 0, 0, 0,
        ffn_b2, 0, dln, 1, ROWS, 512, 1024);

    (void)in_sizes; (void)n_in; (void)out_size;
}

// round 8
// speedup vs baseline: 1.2239x; 1.0310x over previous
#include <cuda_runtime.h>
#include <cuda_bf16.h>
#include <cstdint>
#include <math.h>

#define BATCH 8
#define LSEQ  1024
#define DIM   512
#define DI    1024
#define DS    16
#define HID   1024
#define ROWS  (BATCH*LSEQ)    // 8192

typedef __nv_bfloat16 bf16;

// ---------------- fp32 scratch ----------------
__device__ float g_pos    [LSEQ*DIM];
__device__ float g_pos_mix[LSEQ*DIM];
__device__ float g_xz     [ROWS*4096];
__device__ float g_xc     [2*ROWS*DI];
__device__ float g_proj   [2*ROWS*64];
__device__ float g_dsp    [2*ROWS*DI];
__device__ float g_dmix   [ROWS*DIM];
__device__ float g_dln    [ROWS*DIM];

// ---------------- bf16 hi/lo scratch ----------------
__device__ __align__(16) bf16 hl_scan_in[2*ROWS*DIM];
__device__ __align__(16) bf16 hl_pos_h  [2*LSEQ*DIM];
__device__ __align__(16) bf16 hl_pos    [2*LSEQ*DIM];
__device__ __align__(16) bf16 hl_w_pos2 [2*DIM*DIM];
__device__ __align__(16) bf16 hl_w_pmix [2*DIM*DIM];
__device__ __align__(16) bf16 hl_w_mixA [2*2*DIM*DIM];
__device__ __align__(16) bf16 hl_wT_out [2*2*DI*DIM];
__device__ __align__(16) bf16 hl_w_in   [2*4096*DIM];
__device__ __align__(16) bf16 hl_w_xp   [2*2*64*DI];
__device__ __align__(16) bf16 hl_w_dt   [2*2*DI*32];
__device__ __align__(16) bf16 hl_w_f1   [2*HID*DIM];
__device__ __align__(16) bf16 hl_w_f2   [2*DIM*HID];
__device__ __align__(16) bf16 hl_xc     [2*2*ROWS*DI];
__device__ __align__(16) bf16 hl_proj   [2*2*ROWS*64];
__device__ __align__(16) bf16 hl_ycat   [2*ROWS*2048];
__device__ __align__(16) bf16 hl_wc     [2*DIM*2048];
__device__ __align__(16) bf16 hl_lnf    [2*ROWS*DIM];
__device__ __align__(16) bf16 hl_h1     [2*ROWS*HID];

// ---------------- math helpers ----------------
__device__ __forceinline__ float geluf(float x) {
    return 0.5f * x * (1.0f + erff(x * 0.70710678118654752440f));
}
__device__ __forceinline__ float siluf(float x) { return x / (1.0f + __expf(-x)); }
__device__ __forceinline__ float softplusf(float x) { return (x > 20.0f) ? x : log1pf(__expf(x)); }
__device__ __forceinline__ void splitf(float v, bf16& h, bf16& l) {
    h = __float2bfloat16(v);
    l = __float2bfloat16(v - __bfloat162float(h));
}

// ---------------- PTX helpers ----------------
__device__ __forceinline__ void mma16816(float* d, const uint32_t* a, uint32_t b0, uint32_t b1) {
    asm volatile(
        "mma.sync.aligned.m16n8k16.row.col.f32.bf16.bf16.f32 "
        "{%0,%1,%2,%3},{%4,%5,%6,%7},{%8,%9},{%0,%1,%2,%3};\n"
        : "+f"(d[0]), "+f"(d[1]), "+f"(d[2]), "+f"(d[3])
        : "r"(a[0]), "r"(a[1]), "r"(a[2]), "r"(a[3]), "r"(b0), "r"(b1));
}
__device__ __forceinline__ void ldsm4(uint32_t* r, uint32_t addr) {
    asm volatile("ldmatrix.sync.aligned.m8n8.x4.shared.b16 {%0,%1,%2,%3}, [%4];\n"
                 : "=r"(r[0]), "=r"(r[1]), "=r"(r[2]), "=r"(r[3]) : "r"(addr));
}
__device__ __forceinline__ void cp16(uint32_t dst, const void* src, bool pred) {
    int sz = pred ? 16 : 0;
    asm volatile("cp.async.cg.shared.global [%0], [%1], 16, %2;\n"
                 :: "r"(dst), "l"(src), "r"(sz) : "memory");
}
__device__ __forceinline__ void cp_commit() { asm volatile("cp.async.commit_group;\n" ::: "memory"); }
__device__ __forceinline__ void cp_wait1()  { asm volatile("cp.async.wait_group 1;\n" ::: "memory"); }

// ---------------- mma.sync GEMM (pre-split bf16 hi/lo, 3-term) ----------------
// R3 structure + __launch_bounds__(256, 2) — isolated 2-CTA/SM experiment.
// C[m,n] = sum_k A[m,k]*B[n,k];  A=(M,K), B=(N,K), hi/lo planes.
// EPI: 0 none, 1 gelu, 3 softplus, 4 +aux[(m%auxMod)*ldc+n], 5 +aux[m*ldc+n]
// OUT: 0 fp32 only, 1 fp32 + hi/lo, 2 hi/lo only
#define BK_STAGES 3
#define SMEM_BYTES (BK_STAGES*32768)

template<int EPI, int OUT>
__global__ void __launch_bounds__(256, 2)
bgemm(const bf16* __restrict__ Ah, const bf16* __restrict__ Al, int lda, long long sA,
      const bf16* __restrict__ Bh, const bf16* __restrict__ Bl, int ldb, long long sB,
      float* __restrict__ C, int ldc, long long sC,
      bf16* __restrict__ Ch, long long planeC, int ldch, long long sCh,
      const float* __restrict__ bias, long long sBias,
      const float* __restrict__ aux, int auxMod,
      int M, int N, int K)
{
    extern __shared__ char smd[];
    const int zi = blockIdx.z;
    Ah += (size_t)zi * sA; Al += (size_t)zi * sA;
    Bh += (size_t)zi * sB; Bl += (size_t)zi * sB;
    if (OUT != 2) C += (size_t)zi * sC;
    if (OUT != 0) Ch += (size_t)zi * sCh;
    const float* bp = bias ? (bias + (size_t)zi * sBias) : nullptr;

    const int bm = blockIdx.y * 128;
    const int bn = blockIdx.x * 128;
    const int tid = threadIdx.x, lane = tid & 31, warp = tid >> 5;
    const int wm = warp & 1, wn = warp >> 1;

    const uint32_t smem_base = (uint32_t)__cvta_generic_to_shared(smd);

    auto load_stage = [&](int s, int kt) {
        const int k0 = kt * 32;
        const uint32_t As = smem_base + s * 32768;
        const uint32_t Bs = As + 16384;
#pragma unroll
        for (int i = 0; i < 4; i++) {
            int lin = i * 256 + tid;
            int row = lin >> 3, ch = lin & 7;
            const bf16* srcA = ((ch & 4) ? Al : Ah) + (size_t)(bm + row) * lda + k0 + (ch & 3) * 8;
            cp16(As + row * 128 + ((ch ^ (row & 7)) * 16), srcA, true);
        }
#pragma unroll
        for (int i = 0; i < 4; i++) {
            int lin = i * 256 + tid;
            int row = lin >> 3, ch = lin & 7;
            bool ok = (bn + row) < N;
            const bf16* srcB = ((ch & 4) ? Bl : Bh) +
                               (ok ? ((size_t)(bn + row) * ldb + k0 + (ch & 3) * 8) : 0);
            cp16(Bs + row * 128 + ((ch ^ (row & 7)) * 16), srcB, ok);
        }
    };

    float acc[4][4][4];
#pragma unroll
    for (int i = 0; i < 4; i++)
#pragma unroll
        for (int j = 0; j < 4; j++)
#pragma unroll
            for (int q = 0; q < 4; q++) acc[i][j][q] = 0.0f;

    const int nk = K / 32;
    if (nk > 0) load_stage(0, 0);
    cp_commit();
    if (nk > 1) load_stage(1, 1);
    cp_commit();

    const int g  = lane >> 3;
    const int lr = lane & 7;
    const int aRow0 = wm * 64 + (g & 1) * 8 + lr;
    const int bRow0 = wn * 32 + (g & 1) * 8 + lr;
    const int chHi  = (g >> 1);

    for (int kt = 0; kt < nk; kt++) {
        cp_wait1();
        __syncthreads();
        const uint32_t As = smem_base + (kt % BK_STAGES) * 32768;
        const uint32_t Bs = As + 16384;

#pragma unroll
        for (int step = 0; step < 2; step++) {
            uint32_t ah[4][4], al[4][4], bh[2][4], bl[2][4];
            const int cH = ((step * 2 + chHi) ^ lr) * 16;
            const int cL = ((4 + step * 2 + chHi) ^ lr) * 16;
#pragma unroll
            for (int mt = 0; mt < 4; mt++) {
                uint32_t rb = As + (uint32_t)(aRow0 + mt * 16) * 128;
                ldsm4(ah[mt], rb + cH);
                ldsm4(al[mt], rb + cL);
            }
#pragma unroll
            for (int p = 0; p < 2; p++) {
                uint32_t rb = Bs + (uint32_t)(bRow0 + p * 16) * 128;
                ldsm4(bh[p], rb + cH);
                ldsm4(bl[p], rb + cL);
            }
#pragma unroll
            for (int nt = 0; nt < 4; nt++) {
                const int p = nt >> 1, o = nt & 1;
                const uint32_t b0h = bh[p][o], b1h = bh[p][o + 2];
                const uint32_t b0l = bl[p][o], b1l = bl[p][o + 2];
#pragma unroll
                for (int mt = 0; mt < 4; mt++) {
                    mma16816(acc[mt][nt], ah[mt], b0h, b1h);
                    mma16816(acc[mt][nt], ah[mt], b0l, b1l);
                    mma16816(acc[mt][nt], al[mt], b0h, b1h);
                }
            }
        }
        __syncthreads();
        if (kt + 2 < nk) load_stage((kt + 2) % BK_STAGES, kt + 2);
        cp_commit();
    }

    const int r_ep = lane >> 2, c_ep = lane & 3;
#pragma unroll
    for (int mt = 0; mt < 4; mt++) {
        const int m0 = bm + wm * 64 + mt * 16 + r_ep;
#pragma unroll
        for (int nt = 0; nt < 4; nt++) {
            const int n0 = bn + wn * 32 + nt * 8 + 2 * c_ep;
#pragma unroll
            for (int half = 0; half < 2; half++) {
                const int m = m0 + half * 8;
#pragma unroll
                for (int q = 0; q < 2; q++) {
                    const int n = n0 + q;
                    if (n < N) {
                        float v = acc[mt][nt][half * 2 + q];
                        if (bp) v += bp[n];
                        if (EPI == 1)      v = geluf(v);
                        else if (EPI == 3) v = softplusf(v);
                        else if (EPI == 4) v += aux[(size_t)(m % auxMod) * ldc + n];
                        else if (EPI == 5) v += aux[(size_t)m * ldc + n];
                        if (OUT != 2) C[(size_t)m * ldc + n] = v;
                        if (OUT != 0) {
                            bf16 h, l; splitf(v, h, l);
                            size_t o = (size_t)m * ldch + n;
                            Ch[o] = h; Ch[planeC + o] = l;
                        }
                    }
                }
            }
        }
    }
}

// ---------------- fp32 -> hi/lo converts ----------------
__global__ void conv_hl_k(const float* __restrict__ src, int ld, int cols, int total,
                          long long plane, bf16* __restrict__ dst)
{
    int i = blockIdx.x * 256 + threadIdx.x;
    if (i >= total) return;
    int r = i / cols, c = i - r * cols;
    float v = src[(size_t)r * ld + c];
    bf16 h, l; splitf(v, h, l);
    dst[i] = h; dst[plane + i] = l;
}
__global__ void conv_hl_t_k(const float* __restrict__ src, int J, int E,
                            long long plane, bf16* __restrict__ dst)
{
    int i = blockIdx.x * 256 + threadIdx.x;
    if (i >= J * E) return;
    int e = i / J, j = i - e * J;
    float v = src[(size_t)j * E + e];
    bf16 h, l; splitf(v, h, l);
    dst[i] = h; dst[plane + i] = l;
}

// ---------------- positional features ----------------
__global__ void pos_hidden_k(const float* __restrict__ w1, const float* __restrict__ b1,
                             bf16* __restrict__ ph)
{
    int idx = blockIdx.x * 256 + threadIdx.x;
    if (idx >= LSEQ * DIM) return;
    int t = idx >> 9;
    int c = idx & 511;
    int y = t >> 5, x = t & 31;
    const float PI = 3.14159265358979323846f;
    float yy = ((y + 0.5f) / 32.0f) * 2.0f - 1.0f;
    float xx = ((x + 0.5f) / 32.0f) * 2.0f - 1.0f;
    float f2 = sinf(PI * yy), f3 = cosf(PI * yy);
    float f4 = sinf(PI * xx), f5 = cosf(PI * xx);
    const float* w = w1 + c * 6;
    float v = b1[c] + yy * w[0] + xx * w[1] + f2 * w[2] + f3 * w[3] + f4 * w[4] + f5 * w[5];
    v = geluf(v);
    bf16 h, l; splitf(v, h, l);
    ph[idx] = h; ph[LSEQ * DIM + idx] = l;
}

// ---------------- LN(tokens) + pos -> hi/lo ----------------
__global__ void ln_add_pos_k(const float* __restrict__ x,
                             const float* __restrict__ g, const float* __restrict__ b,
                             const float* __restrict__ pos, bf16* __restrict__ out)
{
    __shared__ float sh[32];
    const int row = blockIdx.x;
    const int tid = threadIdx.x;
    const float* xr = x + (size_t)row * DIM;
    float v0 = xr[tid], v1 = xr[tid + 256];

    float s = v0 + v1, q = v0 * v0 + v1 * v1;
#pragma unroll
    for (int o = 16; o; o >>= 1) {
        s += __shfl_xor_sync(0xffffffffu, s, o);
        q += __shfl_xor_sync(0xffffffffu, q, o);
    }
    if ((tid & 31) == 0) { sh[tid >> 5] = s; sh[8 + (tid >> 5)] = q; }
    __syncthreads();
    if (tid == 0) {
        float S = 0.f, Q = 0.f;
        for (int i = 0; i < 8; i++) { S += sh[i]; Q += sh[8 + i]; }
        float mu = S * (1.0f / DIM);
        float var = Q * (1.0f / DIM) - mu * mu;
        sh[16] = mu; sh[17] = rsqrtf(var + 1e-5f);
    }
    __syncthreads();
    const float mu = sh[16], rs = sh[17];
    const int t = row & (LSEQ - 1);
    const float* pr = pos + (size_t)t * DIM;
    const long long plane = (long long)ROWS * DIM;
    float r0 = (v0 - mu) * rs * g[tid]       + b[tid]       + pr[tid];
    float r1 = (v1 - mu) * rs * g[tid + 256] + b[tid + 256] + pr[tid + 256];
    bf16 h, l;
    size_t o0 = (size_t)row * DIM + tid;
    splitf(r0, h, l); out[o0] = h; out[plane + o0] = l;
    splitf(r1, h, l); out[o0 + 256] = h; out[plane + o0 + 256] = l;
}

// ---------------- causal conv + SiLU ----------------
__global__ void conv_silu_k(const float* __restrict__ xz,
                            const float* __restrict__ cw, const float* __restrict__ cb,
                            float* __restrict__ xc, bf16* __restrict__ xch)
{
    size_t idx = (size_t)blockIdx.x * 256 + threadIdx.x;
    int d   = (int)(idx & 1023);
    int row = (int)((idx >> 10) & (ROWS - 1));
    int dir = (int)(idx >> 23);
    int t = row & (LSEQ - 1);
    int b = row >> 10;

    float acc = cb[dir * DI + d];
#pragma unroll
    for (int k = 0; k < 4; k++) {
        int off = dir ? (3 - k) : (k - 3);
        int tt = t + off;
        if (tt >= 0 && tt < LSEQ) {
            float v = xz[((size_t)(b * LSEQ + tt)) * 4096 + dir * 2048 + d];
            acc = fmaf(cw[(dir * DI + d) * 4 + k], v, acc);
        }
    }
    float v = siluf(acc);
    xc[idx] = v;
    bf16 h, l; splitf(v, h, l);
    xch[idx] = h; xch[(size_t)2 * ROWS * DI + idx] = l;
}

// ---------------- selective scan (register-lean exp fast-path) ----------------
__global__ void scan_k(const float* __restrict__ dsp, const float* __restrict__ xc,
                       const float* __restrict__ proj, const float* __restrict__ xz,
                       const float* __restrict__ A_log, const float* __restrict__ Dp,
                       bf16* __restrict__ ycat)
{
    const int dir = blockIdx.z;
    const int b   = blockIdx.y;
    const int d   = blockIdx.x * 128 + threadIdx.x;

    float a[DS];
    bool fast = true;
#pragma unroll
    for (int s = 0; s < DS; s++) {
        a[s] = -expf(A_log[((size_t)dir * DI + d) * DS + s]);
        fast = fast && (fabsf(a[s] + (float)(s + 1)) < 1e-4f * (float)(s + 1));
    }
    const float Dv = Dp[dir * DI + d];

    float h[DS];
#pragma unroll
    for (int s = 0; s < DS; s++) h[s] = 0.0f;

    const size_t base_row = (size_t)dir * ROWS + (size_t)b * LSEQ;
    const long long plane = (long long)ROWS * 2048;
    __shared__ float sBC[64][32];

    for (int tc = 0; tc < LSEQ; tc += 64) {
        __syncthreads();
        for (int i = threadIdx.x; i < 64 * 32; i += 128) {
            int step = tc + (i >> 5);
            int c = i & 31;
            int r = dir ? (LSEQ - 1 - step) : step;
            sBC[i >> 5][c] = proj[(base_row + r) * 64 + 32 + c];
        }
        __syncthreads();

        if (fast) {
            for (int i = 0; i < 64; i++) {
                int step = tc + i;
                int r = dir ? (LSEQ - 1 - step) : step;
                size_t ro = (base_row + r) * (size_t)DI + d;
                float delta = dsp[ro];
                float x     = xc[ro];
                float dx    = delta * x;
                float y = 0.0f;
                float e1 = __expf(-delta);
                float ep = e1;
#pragma unroll
                for (int s = 0; s < DS; s++) {
                    h[s] = fmaf(h[s], ep, dx * sBC[i][s]);
                    y = fmaf(h[s], sBC[i][16 + s], y);
                    ep *= e1;
                }
                float z = xz[((size_t)(b * LSEQ + r)) * 4096 + dir * 2048 + DI + d];
                float outv = (y + x * Dv) * siluf(z);
                bf16 hh, ll; splitf(outv, hh, ll);
                size_t oo = ((size_t)(b * LSEQ + r)) * 2048 + dir * DI + d;
                ycat[oo] = hh; ycat[plane + oo] = ll;
            }
        } else {
            for (int i = 0; i < 64; i++) {
                int step = tc + i;
                int r = dir ? (LSEQ - 1 - step) : step;
                size_t ro = (base_row + r) * (size_t)DI + d;
                float delta = dsp[ro];
                float x     = xc[ro];
                float dx    = delta * x;
                float y = 0.0f;
#pragma unroll
                for (int s = 0; s < DS; s++) {
                    float e = __expf(delta * a[s]);
                    h[s] = fmaf(h[s], e, dx * sBC[i][s]);
                    y = fmaf(h[s], sBC[i][16 + s], y);
                }
                float z = xz[((size_t)(b * LSEQ + r)) * 4096 + dir * 2048 + DI + d];
                float outv = (y + x * Dv) * siluf(z);
                bf16 hh, ll; splitf(outv, hh, ll);
                size_t oo = ((size_t)(b * LSEQ + r)) * 2048 + dir * DI + d;
                ycat[oo] = hh; ycat[plane + oo] = ll;
            }
        }
    }
}

// ---------------- dual LayerNorm ----------------
__global__ void ln_dual_k(const float* __restrict__ in,
                          const float* __restrict__ g1, const float* __restrict__ b1,
                          const float* __restrict__ g2, const float* __restrict__ b2,
                          float* __restrict__ out1, bf16* __restrict__ out2)
{
    __shared__ float sh[32];
    const int row = blockIdx.x;
    const int tid = threadIdx.x;
    const float* xr = in + (size_t)row * DIM;
    float v0 = xr[tid], v1 = xr[tid + 256];

    float s = v0 + v1, q = v0 * v0 + v1 * v1;
#pragma unroll
    for (int o = 16; o; o >>= 1) {
        s += __shfl_xor_sync(0xffffffffu, s, o);
        q += __shfl_xor_sync(0xffffffffu, q, o);
    }
    if ((tid & 31) == 0) { sh[tid >> 5] = s; sh[8 + (tid >> 5)] = q; }
    __syncthreads();
    if (tid == 0) {
        float S = 0.f, Q = 0.f;
        for (int i = 0; i < 8; i++) { S += sh[i]; Q += sh[8 + i]; }
        float mu = S * (1.0f / DIM);
        float var = Q * (1.0f / DIM) - mu * mu;
        sh[16] = mu; sh[17] = rsqrtf(var + 1e-5f);
    }
    __syncthreads();
    float mu = sh[16], rs = sh[17];
    float x0 = (v0 - mu) * rs * g1[tid]       + b1[tid];
    float x1 = (v1 - mu) * rs * g1[tid + 256] + b1[tid + 256];
    float* o1 = out1 + (size_t)row * DIM;
    o1[tid] = x0; o1[tid + 256] = x1;

    __syncthreads();
    s = x0 + x1; q = x0 * x0 + x1 * x1;
#pragma unroll
    for (int o = 16; o; o >>= 1) {
        s += __shfl_xor_sync(0xffffffffu, s, o);
        q += __shfl_xor_sync(0xffffffffu, q, o);
    }
    if ((tid & 31) == 0) { sh[tid >> 5] = s; sh[8 + (tid >> 5)] = q; }
    __syncthreads();
    if (tid == 0) {
        float S = 0.f, Q = 0.f;
        for (int i = 0; i < 8; i++) { S += sh[i]; Q += sh[8 + i]; }
        float mu2 = S * (1.0f / DIM);
        float var2 = Q * (1.0f / DIM) - mu2 * mu2;
        sh[16] = mu2; sh[17] = rsqrtf(var2 + 1e-5f);
    }
    __syncthreads();
    float mu2 = sh[16], rs2 = sh[17];
    const long long plane = (long long)ROWS * DIM;
    float y0 = (x0 - mu2) * rs2 * g2[tid]       + b2[tid];
    float y1 = (x1 - mu2) * rs2 * g2[tid + 256] + b2[tid + 256];
    bf16 h, l;
    size_t o0 = (size_t)row * DIM + tid;
    splitf(y0, h, l); out2[o0] = h; out2[plane + o0] = l;
    splitf(y1, h, l); out2[o0 + 256] = h; out2[plane + o0 + 256] = l;
}

// ---------------- host launcher ----------------
extern "C" void kernel_launch(void* const* d_in, const int* in_sizes, int n_in,
                              void* d_out, int out_size)
{
    const float* tokens    = (const float*)d_in[0];
    const float* in_g      = (const float*)d_in[3];
    const float* in_b      = (const float*)d_in[4];
    const float* pos_w1    = (const float*)d_in[5];
    const float* pos_b1    = (const float*)d_in[6];
    const float* pos_w2    = (const float*)d_in[7];
    const float* pos_b2    = (const float*)d_in[8];
    const float* m_in_w    = (const float*)d_in[9];
    const float* m_conv_w  = (const float*)d_in[10];
    const float* m_conv_b  = (const float*)d_in[11];
    const float* m_xproj_w = (const float*)d_in[12];
    const float* m_dt_w    = (const float*)d_in[13];
    const float* m_dt_b    = (const float*)d_in[14];
    const float* m_A_log   = (const float*)d_in[15];
    const float* m_D       = (const float*)d_in[16];
    const float* m_out_w   = (const float*)d_in[17];
    const float* mix_w     = (const float*)d_in[18];
    const float* mix_b     = (const float*)d_in[19];
    const float* dn_g      = (const float*)d_in[20];
    const float* dn_b      = (const float*)d_in[21];
    const float* fn_g      = (const float*)d_in[22];
    const float* fn_b      = (const float*)d_in[23];
    const float* ffn_w1    = (const float*)d_in[24];
    const float* ffn_b1    = (const float*)d_in[25];
    const float* ffn_w2    = (const float*)d_in[26];
    const float* ffn_b2    = (const float*)d_in[27];
    float* out = (float*)d_out;

    float *pos, *pos_mix, *xz, *xc, *proj, *dsp, *dmix, *dln;
    bf16 *sin_hl, *posh_hl, *pos_hl, *wpos2, *wpmix, *wmixA, *wTout, *win, *wxp, *wdt, *wf1, *wf2;
    bf16 *xc_hl, *proj_hl, *ycat_hl, *wc_hl, *lnf_hl, *h1_hl;
    cudaGetSymbolAddress((void**)&pos,     g_pos);
    cudaGetSymbolAddress((void**)&pos_mix, g_pos_mix);
    cudaGetSymbolAddress((void**)&xz,      g_xz);
    cudaGetSymbolAddress((void**)&xc,      g_xc);
    cudaGetSymbolAddress((void**)&proj,    g_proj);
    cudaGetSymbolAddress((void**)&dsp,     g_dsp);
    cudaGetSymbolAddress((void**)&dmix,    g_dmix);
    cudaGetSymbolAddress((void**)&dln,     g_dln);
    cudaGetSymbolAddress((void**)&sin_hl,  hl_scan_in);
    cudaGetSymbolAddress((void**)&posh_hl, hl_pos_h);
    cudaGetSymbolAddress((void**)&pos_hl,  hl_pos);
    cudaGetSymbolAddress((void**)&wpos2,   hl_w_pos2);
    cudaGetSymbolAddress((void**)&wpmix,   hl_w_pmix);
    cudaGetSymbolAddress((void**)&wmixA,   hl_w_mixA);
    cudaGetSymbolAddress((void**)&wTout,   hl_wT_out);
    cudaGetSymbolAddress((void**)&win,     hl_w_in);
    cudaGetSymbolAddress((void**)&wxp,     hl_w_xp);
    cudaGetSymbolAddress((void**)&wdt,     hl_w_dt);
    cudaGetSymbolAddress((void**)&wf1,     hl_w_f1);
    cudaGetSymbolAddress((void**)&wf2,     hl_w_f2);
    cudaGetSymbolAddress((void**)&xc_hl,   hl_xc);
    cudaGetSymbolAddress((void**)&proj_hl, hl_proj);
    cudaGetSymbolAddress((void**)&ycat_hl, hl_ycat);
    cudaGetSymbolAddress((void**)&wc_hl,   hl_wc);
    cudaGetSymbolAddress((void**)&lnf_hl,  hl_lnf);
    cudaGetSymbolAddress((void**)&h1_hl,   hl_h1);

    cudaFuncSetAttribute(bgemm<0,0>, cudaFuncAttributeMaxDynamicSharedMemorySize, SMEM_BYTES);
    cudaFuncSetAttribute(bgemm<0,1>, cudaFuncAttributeMaxDynamicSharedMemorySize, SMEM_BYTES);
    cudaFuncSetAttribute(bgemm<0,2>, cudaFuncAttributeMaxDynamicSharedMemorySize, SMEM_BYTES);
    cudaFuncSetAttribute(bgemm<3,0>, cudaFuncAttributeMaxDynamicSharedMemorySize, SMEM_BYTES);
    cudaFuncSetAttribute(bgemm<4,0>, cudaFuncAttributeMaxDynamicSharedMemorySize, SMEM_BYTES);
    cudaFuncSetAttribute(bgemm<1,2>, cudaFuncAttributeMaxDynamicSharedMemorySize, SMEM_BYTES);
    cudaFuncSetAttribute(bgemm<5,0>, cudaFuncAttributeMaxDynamicSharedMemorySize, SMEM_BYTES);

    // ---- launch order arranged so launch #6 (ncu -s 5 -c 1) is the xz GEMM ----
    // 1: wpos2 convert
    conv_hl_k<<<1024, 256>>>(pos_w2, 512, 512, 512*512, 512*512, wpos2);
    // 2: pos hidden
    pos_hidden_k<<<2048, 256>>>(pos_w1, pos_b1, posh_hl);
    // 3: pos = gelu_h @ pos_w2^T + b2
    bgemm<0,1><<<dim3(4,8,1), 256, SMEM_BYTES>>>(
        posh_hl, posh_hl + LSEQ*DIM, 512, 0,  wpos2, wpos2 + 512*512, 512, 0,
        pos, 512, 0,  pos_hl, (long long)LSEQ*DIM, 512, 0,
        pos_b2, 0, nullptr, 1, LSEQ, 512, 512);
    // 4: in_w convert
    conv_hl_k<<<8192, 256>>>(m_in_w, 512, 512, 4096*512, (long long)4096*512, win);
    // 5: scan_in = LN(tokens) + pos
    ln_add_pos_k<<<ROWS, 256>>>(tokens, in_g, in_b, pos, sin_hl);
    // 6: xz = scan_in @ in_w^T  <-- PROFILED LAUNCH
    bgemm<0,0><<<dim3(32,64,1), 256, SMEM_BYTES>>>(
        sin_hl, sin_hl + (long long)ROWS*DIM, 512, 0,
        win, win + (long long)4096*512, 512, 0,
        xz, 4096, 0, nullptr, 0, 0, 0,
        nullptr, 0, nullptr, 1, ROWS, 4096, 512);

    // ---- remaining converts ----
    conv_hl_k<<<1024, 256>>>(mix_w + 1024, 1536, 512, 512*512, 512*512, wpmix);
    conv_hl_k<<<1024, 256>>>(mix_w,        1536, 512, 512*512, (long long)2*512*512, wmixA);
    conv_hl_k<<<1024, 256>>>(mix_w + 512,  1536, 512, 512*512, (long long)2*512*512, wmixA + 512*512);
    conv_hl_t_k<<<2048, 256>>>(m_out_w,            512, 1024, (long long)2*1024*512, wTout);
    conv_hl_t_k<<<2048, 256>>>(m_out_w + 512*1024, 512, 1024, (long long)2*1024*512, wTout + 1024*512);
    conv_hl_k<<<512,  256>>>(m_xproj_w, 1024, 1024, 128*1024, (long long)128*1024, wxp);
    conv_hl_k<<<256,  256>>>(m_dt_w,    32, 32, 2048*32, (long long)2048*32, wdt);
    conv_hl_k<<<2048, 256>>>(ffn_w1,    512, 512, 1024*512, (long long)1024*512, wf1);
    conv_hl_k<<<2048, 256>>>(ffn_w2,    1024, 1024, 512*1024, (long long)512*1024, wf2);

    // pos_mix = pos @ mix_w[:,1024:1536]^T + mix_b
    bgemm<0,0><<<dim3(4,8,1), 256, SMEM_BYTES>>>(
        pos_hl, pos_hl + LSEQ*DIM, 512, 0,  wpmix, wpmix + 512*512, 512, 0,
        pos_mix, 512, 0,  nullptr, 0, 0, 0,
        mix_b, 0, nullptr, 1, LSEQ, 512, 512);
    // Wc[dir] = mix_w_slice @ out_w[dir]
    bgemm<0,2><<<dim3(8,4,2), 256, SMEM_BYTES>>>(
        wmixA, wmixA + (long long)2*512*512, 512, (long long)512*512,
        wTout, wTout + (long long)2*1024*512, 512, (long long)1024*512,
        nullptr, 0, 0,
        wc_hl, (long long)512*2048, 2048, 1024,
        nullptr, 0, nullptr, 1, 512, 1024, 512);

    conv_silu_k<<<(2*ROWS*DI)/256, 256>>>(xz, m_conv_w, m_conv_b, xc, xc_hl);
    bgemm<0,1><<<dim3(1,64,2), 256, SMEM_BYTES>>>(
        xc_hl, xc_hl + (long long)2*ROWS*DI, 1024, (long long)ROWS*DI,
        wxp, wxp + (long long)128*1024, 1024, (long long)64*1024,
        proj, 64, (long long)ROWS*64,
        proj_hl, (long long)2*ROWS*64, 64, (long long)ROWS*64,
        nullptr, 0, nullptr, 1, ROWS, 64, 1024);
    bgemm<3,0><<<dim3(8,64,2), 256, SMEM_BYTES>>>(
        proj_hl, proj_hl + (long long)2*ROWS*64, 64, (long long)ROWS*64,
        wdt, wdt + (long long)2048*32, 32, (long long)1024*32,
        dsp, 1024, (long long)ROWS*DI, nullptr, 0, 0, 0,
        m_dt_b, 1024, nullptr, 1, ROWS, 1024, 32);
    scan_k<<<dim3(DI/128, BATCH, 2), 128>>>(dsp, xc, proj, xz, m_A_log, m_D, ycat_hl);
    bgemm<4,0><<<dim3(4,64,1), 256, SMEM_BYTES>>>(
        ycat_hl, ycat_hl + (long long)ROWS*2048, 2048, 0,
        wc_hl, wc_hl + (long long)512*2048, 2048, 0,
        dmix, 512, 0, nullptr, 0, 0, 0,
        nullptr, 0, pos_mix, LSEQ, ROWS, 512, 2048);
    ln_dual_k<<<ROWS, 256>>>(dmix, dn_g, dn_b, fn_g, fn_b, dln, lnf_hl);
    bgemm<1,2><<<dim3(8,64,1), 256, SMEM_BYTES>>>(
        lnf_hl, lnf_hl + (long long)ROWS*DIM, 512, 0,
        wf1, wf1 + (long long)1024*512, 512, 0,
        nullptr, 1024, 0,
        h1_hl, (long long)ROWS*HID, 1024, 0,
        ffn_b1, 0, nullptr, 1, ROWS, 1024, 512);
    bgemm<5,0><<<dim3(4,64,1), 256, SMEM_BYTES>>>(
        h1_hl, h1_hl + (long long)ROWS*HID, 1024, 0,
        wf2, wf2 + (long long)512*1024, 1024, 0,
        out, 512, 0, nullptr, 0, 0, 0,
        ffn_b2, 0, dln, 1, ROWS, 512, 1024);

    (void)in_sizes; (void)n_in; (void)out_size;
}